// round 5
// baseline (speedup 1.0000x reference)
#include <cuda_runtime.h>
#include <math.h>

#define BATCH 256
#define SEQ   512
#define INPUT 64
#define HID   512
#define KC    64
#define PAD   33   // row stride (floats) for transposed smem tiles; 33%32==1 -> conflict-free

// -------- scratch (static device globals; no allocations anywhere) --------
__device__ float g_seq0[(size_t)BATCH * SEQ * HID];  // xp0 (b, t, h)
__device__ float g_h1[(size_t)BATCH * SEQ * HID];    // layer-0 hidden states (b, t, h)
__device__ float g_hA[BATCH * HID];                  // ping
__device__ float g_hB[BATCH * HID];                  // pong
__device__ unsigned          g_bar_count;            // zero-initialized
__device__ volatile unsigned g_bar_gen;              // zero-initialized

// ---------------------------------------------------------------------------
// Software grid barrier: all CTAs must be co-resident (grid <= 148 SMs, 1 CTA/SM
// by smem). Sense-reversing via monotonically increasing generation counter.
__device__ __forceinline__ void grid_barrier(unsigned nblocks) {
    __syncthreads();
    if (threadIdx.x == 0) {
        unsigned gen = g_bar_gen;          // volatile read; program-ordered
        __threadfence();                   // make this CTA's stores visible
        unsigned arrived = atomicAdd(&g_bar_count, 1u);
        if (arrived == nblocks - 1u) {
            *(volatile unsigned*)&g_bar_count = 0u;
            __threadfence();
            g_bar_gen = gen + 1u;          // release
        } else {
            while (g_bar_gen == gen) { }   // spin
            __threadfence();               // acquire
        }
    }
    __syncthreads();
}

__device__ __forceinline__ float4 ldcg4(const float* p) {
    return __ldcg(reinterpret_cast<const float4*>(p));
}

// ---------------------------------------------------------------------------
// xp0[bt][h] = sum_d x[bt][d] * Wih[h][d] + bih[h] + bhh[h]
__global__ __launch_bounds__(256) void xp0_kernel(
    const float* __restrict__ x, const float* __restrict__ Wih,
    const float* __restrict__ bih, const float* __restrict__ bhh,
    float* __restrict__ out)
{
    __shared__ float xs[16][INPUT];
    const int bt0 = blockIdx.x * 16;
    const int tid = threadIdx.x;
    {
        int r  = tid >> 4;
        int c4 = (tid & 15) * 4;
        float4 v = *reinterpret_cast<const float4*>(&x[(size_t)(bt0 + r) * INPUT + c4]);
        xs[r][c4 + 0] = v.x; xs[r][c4 + 1] = v.y;
        xs[r][c4 + 2] = v.z; xs[r][c4 + 3] = v.w;
    }
    __syncthreads();

    #pragma unroll
    for (int hh = 0; hh < 2; hh++) {
        const int h = tid + hh * 256;
        const float bias = bih[h] + bhh[h];
        float acc[16];
        #pragma unroll
        for (int r = 0; r < 16; r++) acc[r] = 0.0f;
        const float4* wrow = reinterpret_cast<const float4*>(&Wih[(size_t)h * INPUT]);
        #pragma unroll
        for (int k4 = 0; k4 < INPUT / 4; k4++) {
            float4 w = wrow[k4];
            #pragma unroll
            for (int r = 0; r < 16; r++) {
                float4 xv = *reinterpret_cast<const float4*>(&xs[r][k4 * 4]);
                acc[r] = fmaf(w.x, xv.x, acc[r]);
                acc[r] = fmaf(w.y, xv.y, acc[r]);
                acc[r] = fmaf(w.z, xv.z, acc[r]);
                acc[r] = fmaf(w.w, xv.w, acc[r]);
            }
        }
        #pragma unroll
        for (int r = 0; r < 16; r++)
            out[(size_t)(bt0 + r) * HID + h] = acc[r] + bias;
    }
}

// ---------------------------------------------------------------------------
// Load a [32 x HID] weight tile transposed into smem: Wt[k*PAD + r] = W[h0+r][k]
__device__ __forceinline__ void load_w_tile(float* Wt, const float* __restrict__ W, int h0) {
    const int tid = threadIdx.x;
    const int lr  = tid >> 4;           // 0..15
    const int lc4 = (tid & 15) * 4;     // 0..60
    #pragma unroll 1
    for (int rr = lr; rr < 32; rr += 16) {
        const float* wrow = &W[(size_t)(h0 + rr) * HID];
        #pragma unroll 1
        for (int c = lc4; c < HID; c += 64) {
            float4 v = *reinterpret_cast<const float4*>(&wrow[c]);
            Wt[(c + 0) * PAD + rr] = v.x;
            Wt[(c + 1) * PAD + rr] = v.y;
            Wt[(c + 2) * PAD + rr] = v.z;
            Wt[(c + 3) * PAD + rr] = v.w;
        }
    }
}

// Stage a [32 x KC] chunk of A transposed: Asm[k*PAD + r] = A[b0+r][kc+k] (L1-bypass)
__device__ __forceinline__ void stage_a_chunk_cg(float* Asm, const float* __restrict__ A,
                                                 long long astride, int b0, int kc) {
    const int tid = threadIdx.x;
    const int lr  = tid >> 4;
    const int lc4 = (tid & 15) * 4;
    float4 v0 = ldcg4(&A[(size_t)(b0 + lr)      * astride + kc + lc4]);
    float4 v1 = ldcg4(&A[(size_t)(b0 + lr + 16) * astride + kc + lc4]);
    Asm[(lc4 + 0) * PAD + lr] = v0.x; Asm[(lc4 + 1) * PAD + lr] = v0.y;
    Asm[(lc4 + 2) * PAD + lr] = v0.z; Asm[(lc4 + 3) * PAD + lr] = v0.w;
    Asm[(lc4 + 0) * PAD + lr + 16] = v1.x; Asm[(lc4 + 1) * PAD + lr + 16] = v1.y;
    Asm[(lc4 + 2) * PAD + lr + 16] = v1.z; Asm[(lc4 + 3) * PAD + lr + 16] = v1.w;
}

__device__ __forceinline__ void stage_a_chunk(float* Asm, const float* __restrict__ A,
                                              long long astride, int b0, int kc) {
    const int tid = threadIdx.x;
    const int lr  = tid >> 4;
    const int lc4 = (tid & 15) * 4;
    float4 v0 = *reinterpret_cast<const float4*>(&A[(size_t)(b0 + lr)      * astride + kc + lc4]);
    float4 v1 = *reinterpret_cast<const float4*>(&A[(size_t)(b0 + lr + 16) * astride + kc + lc4]);
    Asm[(lc4 + 0) * PAD + lr] = v0.x; Asm[(lc4 + 1) * PAD + lr] = v0.y;
    Asm[(lc4 + 2) * PAD + lr] = v0.z; Asm[(lc4 + 3) * PAD + lr] = v0.w;
    Asm[(lc4 + 0) * PAD + lr + 16] = v1.x; Asm[(lc4 + 1) * PAD + lr + 16] = v1.y;
    Asm[(lc4 + 2) * PAD + lr + 16] = v1.z; Asm[(lc4 + 3) * PAD + lr + 16] = v1.w;
}

// Inner product accumulation over one staged chunk.
__device__ __forceinline__ void mm_chunk(const float* Wt, const float* Asm, int kc,
                                         int tx2, int ty2,
                                         float& c00, float& c01, float& c10, float& c11) {
    #pragma unroll
    for (int k = 0; k < KC; k++) {
        float a0 = Asm[k * PAD + ty2];
        float a1 = Asm[k * PAD + ty2 + 1];
        float w0 = Wt[(kc + k) * PAD + tx2];
        float w1 = Wt[(kc + k) * PAD + tx2 + 1];
        c00 = fmaf(a0, w0, c00);
        c01 = fmaf(a0, w1, c01);
        c10 = fmaf(a1, w0, c10);
        c11 = fmaf(a1, w1, c11);
    }
}

// ---------------------------------------------------------------------------
// Persistent layer-0: 512 steps, W_hh0 tile resident in smem, grid barrier per step.
// grid (16, 8) = 128 CTAs x 256 threads. smem = (HID + KC) * PAD floats.
__global__ __launch_bounds__(256) void rnn_layer0_persistent(
    const float* __restrict__ Whh,
    const float* __restrict__ xp,    // (b, t, h), biases already folded in
    float* __restrict__ h1s,         // (b, t, h)
    float* __restrict__ hA, float* __restrict__ hB)
{
    extern __shared__ float smem[];
    float* Wt  = smem;               // [HID][PAD]
    float* Asm = smem + HID * PAD;   // [KC][PAD]

    const int tid = threadIdx.x;
    const int tx2 = (tid & 15) * 2;
    const int ty2 = (tid >> 4) * 2;
    const int h0  = blockIdx.x * 32;
    const int b0  = blockIdx.y * 32;
    const unsigned nblocks = gridDim.x * gridDim.y;

    load_w_tile(Wt, Whh, h0);

    // zero our patch of hA (initial hidden state)
    hA[(size_t)(b0 + ty2)     * HID + h0 + tx2]     = 0.f;
    hA[(size_t)(b0 + ty2)     * HID + h0 + tx2 + 1] = 0.f;
    hA[(size_t)(b0 + ty2 + 1) * HID + h0 + tx2]     = 0.f;
    hA[(size_t)(b0 + ty2 + 1) * HID + h0 + tx2 + 1] = 0.f;

    grid_barrier(nblocks);

    const size_t SEQS = (size_t)SEQ * HID;
    const int bA = b0 + ty2, bB = bA + 1;
    const int hX = h0 + tx2, hY = hX + 1;

    for (int t = 0; t < SEQ; t++) {
        const float* hprev = (t & 1) ? hB : hA;
        float*       hnext = (t & 1) ? hA : hB;

        // prefetch xp for this step's outputs (latency hidden under the GEMM)
        const float* xpt = xp + (size_t)t * HID;
        float p00 = __ldg(&xpt[(size_t)bA * SEQS + hX]);
        float p01 = __ldg(&xpt[(size_t)bA * SEQS + hY]);
        float p10 = __ldg(&xpt[(size_t)bB * SEQS + hX]);
        float p11 = __ldg(&xpt[(size_t)bB * SEQS + hY]);

        float c00 = 0.f, c01 = 0.f, c10 = 0.f, c11 = 0.f;
        #pragma unroll 1
        for (int kc = 0; kc < HID; kc += KC) {
            stage_a_chunk_cg(Asm, hprev, HID, b0, kc);
            __syncthreads();
            mm_chunk(Wt, Asm, kc, tx2, ty2, c00, c01, c10, c11);
            __syncthreads();
        }

        float v00 = tanhf(c00 + p00);
        float v01 = tanhf(c01 + p01);
        float v10 = tanhf(c10 + p10);
        float v11 = tanhf(c11 + p11);

        hnext[(size_t)bA * HID + hX] = v00;
        hnext[(size_t)bA * HID + hY] = v01;
        hnext[(size_t)bB * HID + hX] = v10;
        hnext[(size_t)bB * HID + hY] = v11;

        float* h1t = h1s + (size_t)t * HID;
        h1t[(size_t)bA * SEQS + hX] = v00;
        h1t[(size_t)bA * SEQS + hY] = v01;
        h1t[(size_t)bB * SEQS + hX] = v10;
        h1t[(size_t)bB * SEQS + hY] = v11;

        grid_barrier(nblocks);
    }
}

// ---------------------------------------------------------------------------
// Persistent layer-1: input GEMM fused (K = 1024 total). Two W tiles resident.
// smem = (2*HID + KC) * PAD floats (~144 KB).
__global__ __launch_bounds__(256) void rnn_layer1_persistent(
    const float* __restrict__ Wih, const float* __restrict__ Whh,
    const float* __restrict__ bih, const float* __restrict__ bhh,
    const float* __restrict__ h1s, // (b, t, h)
    float* __restrict__ hA, float* __restrict__ hB)
{
    extern __shared__ float smem[];
    float* Wt1 = smem;                    // Wih tile [HID][PAD]
    float* Wt2 = smem + HID * PAD;        // Whh tile [HID][PAD]
    float* Asm = smem + 2 * HID * PAD;    // [KC][PAD]

    const int tid = threadIdx.x;
    const int tx2 = (tid & 15) * 2;
    const int ty2 = (tid >> 4) * 2;
    const int h0  = blockIdx.x * 32;
    const int b0  = blockIdx.y * 32;
    const unsigned nblocks = gridDim.x * gridDim.y;

    load_w_tile(Wt1, Wih, h0);
    load_w_tile(Wt2, Whh, h0);

    const int bA = b0 + ty2, bB = bA + 1;
    const int hX = h0 + tx2, hY = hX + 1;

    const float e0 = bih[hX] + bhh[hX];
    const float e1 = bih[hY] + bhh[hY];

    // zero our patch of hA (initial hidden state for layer 1)
    hA[(size_t)bA * HID + hX] = 0.f;
    hA[(size_t)bA * HID + hY] = 0.f;
    hA[(size_t)bB * HID + hX] = 0.f;
    hA[(size_t)bB * HID + hY] = 0.f;

    grid_barrier(nblocks);

    const size_t SEQS = (size_t)SEQ * HID;

    for (int t = 0; t < SEQ; t++) {
        const float* hprev = (t & 1) ? hB : hA;
        float*       hnext = (t & 1) ? hA : hB;
        const float* a0src = h1s + (size_t)t * HID;   // row stride SEQS (read-only)

        float c00 = 0.f, c01 = 0.f, c10 = 0.f, c11 = 0.f;

        #pragma unroll 1
        for (int kc = 0; kc < HID; kc += KC) {        // source 0: h1_t @ Wih^T
            stage_a_chunk(Asm, a0src, (long long)SEQS, b0, kc);
            __syncthreads();
            mm_chunk(Wt1, Asm, kc, tx2, ty2, c00, c01, c10, c11);
            __syncthreads();
        }
        #pragma unroll 1
        for (int kc = 0; kc < HID; kc += KC) {        // source 1: h_prev @ Whh^T
            stage_a_chunk_cg(Asm, hprev, HID, b0, kc);
            __syncthreads();
            mm_chunk(Wt2, Asm, kc, tx2, ty2, c00, c01, c10, c11);
            __syncthreads();
        }

        float v00 = tanhf(c00 + e0);
        float v01 = tanhf(c01 + e1);
        float v10 = tanhf(c10 + e0);
        float v11 = tanhf(c11 + e1);

        hnext[(size_t)bA * HID + hX] = v00;
        hnext[(size_t)bA * HID + hY] = v01;
        hnext[(size_t)bB * HID + hX] = v10;
        hnext[(size_t)bB * HID + hY] = v11;

        grid_barrier(nblocks);
    }
}

// ---------------------------------------------------------------------------
__global__ __launch_bounds__(128) void fc_kernel(
    const float* __restrict__ h, const float* __restrict__ Wfc,
    const float* __restrict__ bfc, float* __restrict__ out)
{
    const int b = blockIdx.x;
    const int tid = threadIdx.x;
    float s = 0.f;
    for (int k = tid; k < HID; k += 128)
        s = fmaf(h[(size_t)b * HID + k], Wfc[k], s);
    #pragma unroll
    for (int o = 16; o > 0; o >>= 1) s += __shfl_xor_sync(0xffffffffu, s, o);
    __shared__ float red[4];
    if ((tid & 31) == 0) red[tid >> 5] = s;
    __syncthreads();
    if (tid == 0) out[b] = red[0] + red[1] + red[2] + red[3] + bfc[0];
}

// ---------------------------------------------------------------------------
extern "C" void kernel_launch(void* const* d_in, const int* in_sizes, int n_in,
                              void* d_out, int out_size)
{
    const float* x    = (const float*)d_in[0];
    const float* Wih0 = (const float*)d_in[1];
    const float* Whh0 = (const float*)d_in[2];
    const float* bih0 = (const float*)d_in[3];
    const float* bhh0 = (const float*)d_in[4];
    const float* Wih1 = (const float*)d_in[5];
    const float* Whh1 = (const float*)d_in[6];
    const float* bih1 = (const float*)d_in[7];
    const float* bhh1 = (const float*)d_in[8];
    const float* Wfc  = (const float*)d_in[9];
    const float* bfc  = (const float*)d_in[10];
    float* out = (float*)d_out;

    float *seq0, *h1s, *hA, *hB;
    cudaGetSymbolAddress((void**)&seq0, g_seq0);
    cudaGetSymbolAddress((void**)&h1s,  g_h1);
    cudaGetSymbolAddress((void**)&hA,   g_hA);
    cudaGetSymbolAddress((void**)&hB,   g_hB);

    const int smem0 = (HID + KC) * PAD * sizeof(float);          //  ~76 KB
    const int smem1 = (2 * HID + KC) * PAD * sizeof(float);      // ~144 KB
    cudaFuncSetAttribute(rnn_layer0_persistent,
                         cudaFuncAttributeMaxDynamicSharedMemorySize, smem0);
    cudaFuncSetAttribute(rnn_layer1_persistent,
                         cudaFuncAttributeMaxDynamicSharedMemorySize, smem1);

    const dim3 sgrid(HID / 32, BATCH / 32);  // (16, 8) = 128 CTAs, co-resident on 148 SMs

    xp0_kernel<<<(BATCH * SEQ) / 16, 256>>>(x, Wih0, bih0, bhh0, seq0);
    rnn_layer0_persistent<<<sgrid, 256, smem0>>>(Whh0, seq0, h1s, hA, hB);
    rnn_layer1_persistent<<<sgrid, 256, smem1>>>(Wih1, Whh1, bih1, bhh1, h1s, hA, hB);
    // SEQ-1 = 511 is odd -> final state in hA
    fc_kernel<<<BATCH, 128>>>(hA, Wfc, bfc, out);

    (void)in_sizes; (void)n_in; (void)out_size;
}

// round 6
// speedup vs baseline: 1.0063x; 1.0063x over previous
#include <cuda_runtime.h>
#include <math.h>

#define BATCH 256
#define SEQ   512
#define INPUT 64
#define HID   512
#define KC    64
#define PAD   33   // row stride (floats) for transposed smem tiles; 33%32==1 -> conflict-free

// -------- scratch (static device globals; no allocations anywhere) --------
__device__ float g_seq0[(size_t)BATCH * SEQ * HID];  // xp0 (b, t, h)
__device__ float g_h1[(size_t)BATCH * SEQ * HID];    // layer-0 hidden states (b, t, h)
__device__ float g_hA[BATCH * HID];                  // ping
__device__ float g_hB[BATCH * HID];                  // pong
__device__ unsigned          g_bar_count;            // zero-initialized
__device__ volatile unsigned g_bar_gen;              // zero-initialized

// ---------------------------------------------------------------------------
// Software grid barrier: all CTAs must be co-resident (grid <= 148 SMs, 1 CTA/SM
// by smem). Sense-reversing via monotonically increasing generation counter.
__device__ __forceinline__ void grid_barrier(unsigned nblocks) {
    __syncthreads();
    if (threadIdx.x == 0) {
        unsigned gen = g_bar_gen;          // volatile read; program-ordered
        __threadfence();                   // make this CTA's stores visible
        unsigned arrived = atomicAdd(&g_bar_count, 1u);
        if (arrived == nblocks - 1u) {
            *(volatile unsigned*)&g_bar_count = 0u;
            __threadfence();
            g_bar_gen = gen + 1u;          // release
        } else {
            while (g_bar_gen == gen) { }   // spin
            __threadfence();               // acquire
        }
    }
    __syncthreads();
}

__device__ __forceinline__ float4 ldcg4(const float* p) {
    return __ldcg(reinterpret_cast<const float4*>(p));
}

// ---------------------------------------------------------------------------
// xp0[bt][h] = sum_d x[bt][d] * Wih[h][d] + bih[h] + bhh[h]
__global__ __launch_bounds__(256) void xp0_kernel(
    const float* __restrict__ x, const float* __restrict__ Wih,
    const float* __restrict__ bih, const float* __restrict__ bhh,
    float* __restrict__ out)
{
    __shared__ float xs[16][INPUT];
    const int bt0 = blockIdx.x * 16;
    const int tid = threadIdx.x;
    {
        int r  = tid >> 4;
        int c4 = (tid & 15) * 4;
        float4 v = *reinterpret_cast<const float4*>(&x[(size_t)(bt0 + r) * INPUT + c4]);
        xs[r][c4 + 0] = v.x; xs[r][c4 + 1] = v.y;
        xs[r][c4 + 2] = v.z; xs[r][c4 + 3] = v.w;
    }
    __syncthreads();

    #pragma unroll
    for (int hh = 0; hh < 2; hh++) {
        const int h = tid + hh * 256;
        const float bias = bih[h] + bhh[h];
        float acc[16];
        #pragma unroll
        for (int r = 0; r < 16; r++) acc[r] = 0.0f;
        const float4* wrow = reinterpret_cast<const float4*>(&Wih[(size_t)h * INPUT]);
        #pragma unroll
        for (int k4 = 0; k4 < INPUT / 4; k4++) {
            float4 w = wrow[k4];
            #pragma unroll
            for (int r = 0; r < 16; r++) {
                float4 xv = *reinterpret_cast<const float4*>(&xs[r][k4 * 4]);
                acc[r] = fmaf(w.x, xv.x, acc[r]);
                acc[r] = fmaf(w.y, xv.y, acc[r]);
                acc[r] = fmaf(w.z, xv.z, acc[r]);
                acc[r] = fmaf(w.w, xv.w, acc[r]);
            }
        }
        #pragma unroll
        for (int r = 0; r < 16; r++)
            out[(size_t)(bt0 + r) * HID + h] = acc[r] + bias;
    }
}

// ---------------------------------------------------------------------------
// Load a [32 x HID] weight tile transposed into smem: Wt[k*PAD + r] = W[h0+r][k]
__device__ __forceinline__ void load_w_tile(float* Wt, const float* __restrict__ W, int h0) {
    const int tid = threadIdx.x;
    const int lr  = tid >> 4;           // 0..15
    const int lc4 = (tid & 15) * 4;     // 0..60
    #pragma unroll 1
    for (int rr = lr; rr < 32; rr += 16) {
        const float* wrow = &W[(size_t)(h0 + rr) * HID];
        #pragma unroll 1
        for (int c = lc4; c < HID; c += 64) {
            float4 v = *reinterpret_cast<const float4*>(&wrow[c]);
            Wt[(c + 0) * PAD + rr] = v.x;
            Wt[(c + 1) * PAD + rr] = v.y;
            Wt[(c + 2) * PAD + rr] = v.z;
            Wt[(c + 3) * PAD + rr] = v.w;
        }
    }
}

// Stage a [32 x KC] chunk of A transposed: Asm[k*PAD + r] = A[b0+r][kc+k] (L1-bypass)
__device__ __forceinline__ void stage_a_chunk_cg(float* Asm, const float* __restrict__ A,
                                                 long long astride, int b0, int kc) {
    const int tid = threadIdx.x;
    const int lr  = tid >> 4;
    const int lc4 = (tid & 15) * 4;
    float4 v0 = ldcg4(&A[(size_t)(b0 + lr)      * astride + kc + lc4]);
    float4 v1 = ldcg4(&A[(size_t)(b0 + lr + 16) * astride + kc + lc4]);
    Asm[(lc4 + 0) * PAD + lr] = v0.x; Asm[(lc4 + 1) * PAD + lr] = v0.y;
    Asm[(lc4 + 2) * PAD + lr] = v0.z; Asm[(lc4 + 3) * PAD + lr] = v0.w;
    Asm[(lc4 + 0) * PAD + lr + 16] = v1.x; Asm[(lc4 + 1) * PAD + lr + 16] = v1.y;
    Asm[(lc4 + 2) * PAD + lr + 16] = v1.z; Asm[(lc4 + 3) * PAD + lr + 16] = v1.w;
}

__device__ __forceinline__ void stage_a_chunk(float* Asm, const float* __restrict__ A,
                                              long long astride, int b0, int kc) {
    const int tid = threadIdx.x;
    const int lr  = tid >> 4;
    const int lc4 = (tid & 15) * 4;
    float4 v0 = *reinterpret_cast<const float4*>(&A[(size_t)(b0 + lr)      * astride + kc + lc4]);
    float4 v1 = *reinterpret_cast<const float4*>(&A[(size_t)(b0 + lr + 16) * astride + kc + lc4]);
    Asm[(lc4 + 0) * PAD + lr] = v0.x; Asm[(lc4 + 1) * PAD + lr] = v0.y;
    Asm[(lc4 + 2) * PAD + lr] = v0.z; Asm[(lc4 + 3) * PAD + lr] = v0.w;
    Asm[(lc4 + 0) * PAD + lr + 16] = v1.x; Asm[(lc4 + 1) * PAD + lr + 16] = v1.y;
    Asm[(lc4 + 2) * PAD + lr + 16] = v1.z; Asm[(lc4 + 3) * PAD + lr + 16] = v1.w;
}

// Inner product accumulation over one staged chunk.
__device__ __forceinline__ void mm_chunk(const float* Wt, const float* Asm, int kc,
                                         int tx2, int ty2,
                                         float& c00, float& c01, float& c10, float& c11) {
    #pragma unroll
    for (int k = 0; k < KC; k++) {
        float a0 = Asm[k * PAD + ty2];
        float a1 = Asm[k * PAD + ty2 + 1];
        float w0 = Wt[(kc + k) * PAD + tx2];
        float w1 = Wt[(kc + k) * PAD + tx2 + 1];
        c00 = fmaf(a0, w0, c00);
        c01 = fmaf(a0, w1, c01);
        c10 = fmaf(a1, w0, c10);
        c11 = fmaf(a1, w1, c11);
    }
}

// ---------------------------------------------------------------------------
// Persistent layer-0: 512 steps, W_hh0 tile resident in smem, grid barrier per step.
// grid (16, 8) = 128 CTAs x 256 threads. smem = (HID + KC) * PAD floats.
__global__ __launch_bounds__(256) void rnn_layer0_persistent(
    const float* __restrict__ Whh,
    const float* __restrict__ xp,    // (b, t, h), biases already folded in
    float* __restrict__ h1s,         // (b, t, h)
    float* __restrict__ hA, float* __restrict__ hB)
{
    extern __shared__ float smem[];
    float* Wt  = smem;               // [HID][PAD]
    float* Asm = smem + HID * PAD;   // [KC][PAD]

    const int tid = threadIdx.x;
    const int tx2 = (tid & 15) * 2;
    const int ty2 = (tid >> 4) * 2;
    const int h0  = blockIdx.x * 32;
    const int b0  = blockIdx.y * 32;
    const unsigned nblocks = gridDim.x * gridDim.y;

    load_w_tile(Wt, Whh, h0);

    // zero our patch of hA (initial hidden state)
    hA[(size_t)(b0 + ty2)     * HID + h0 + tx2]     = 0.f;
    hA[(size_t)(b0 + ty2)     * HID + h0 + tx2 + 1] = 0.f;
    hA[(size_t)(b0 + ty2 + 1) * HID + h0 + tx2]     = 0.f;
    hA[(size_t)(b0 + ty2 + 1) * HID + h0 + tx2 + 1] = 0.f;

    grid_barrier(nblocks);

    const size_t SEQS = (size_t)SEQ * HID;
    const int bA = b0 + ty2, bB = bA + 1;
    const int hX = h0 + tx2, hY = hX + 1;

    for (int t = 0; t < SEQ; t++) {
        const float* hprev = (t & 1) ? hB : hA;
        float*       hnext = (t & 1) ? hA : hB;

        // prefetch xp for this step's outputs (latency hidden under the GEMM)
        const float* xpt = xp + (size_t)t * HID;
        float p00 = __ldg(&xpt[(size_t)bA * SEQS + hX]);
        float p01 = __ldg(&xpt[(size_t)bA * SEQS + hY]);
        float p10 = __ldg(&xpt[(size_t)bB * SEQS + hX]);
        float p11 = __ldg(&xpt[(size_t)bB * SEQS + hY]);

        float c00 = 0.f, c01 = 0.f, c10 = 0.f, c11 = 0.f;
        #pragma unroll 1
        for (int kc = 0; kc < HID; kc += KC) {
            stage_a_chunk_cg(Asm, hprev, HID, b0, kc);
            __syncthreads();
            mm_chunk(Wt, Asm, kc, tx2, ty2, c00, c01, c10, c11);
            __syncthreads();
        }

        float v00 = tanhf(c00 + p00);
        float v01 = tanhf(c01 + p01);
        float v10 = tanhf(c10 + p10);
        float v11 = tanhf(c11 + p11);

        hnext[(size_t)bA * HID + hX] = v00;
        hnext[(size_t)bA * HID + hY] = v01;
        hnext[(size_t)bB * HID + hX] = v10;
        hnext[(size_t)bB * HID + hY] = v11;

        float* h1t = h1s + (size_t)t * HID;
        h1t[(size_t)bA * SEQS + hX] = v00;
        h1t[(size_t)bA * SEQS + hY] = v01;
        h1t[(size_t)bB * SEQS + hX] = v10;
        h1t[(size_t)bB * SEQS + hY] = v11;

        grid_barrier(nblocks);
    }
}

// ---------------------------------------------------------------------------
// Persistent layer-1: input GEMM fused (K = 1024 total). Two W tiles resident.
// smem = (2*HID + KC) * PAD floats (~144 KB).
__global__ __launch_bounds__(256) void rnn_layer1_persistent(
    const float* __restrict__ Wih, const float* __restrict__ Whh,
    const float* __restrict__ bih, const float* __restrict__ bhh,
    const float* __restrict__ h1s, // (b, t, h)
    float* __restrict__ hA, float* __restrict__ hB)
{
    extern __shared__ float smem[];
    float* Wt1 = smem;                    // Wih tile [HID][PAD]
    float* Wt2 = smem + HID * PAD;        // Whh tile [HID][PAD]
    float* Asm = smem + 2 * HID * PAD;    // [KC][PAD]

    const int tid = threadIdx.x;
    const int tx2 = (tid & 15) * 2;
    const int ty2 = (tid >> 4) * 2;
    const int h0  = blockIdx.x * 32;
    const int b0  = blockIdx.y * 32;
    const unsigned nblocks = gridDim.x * gridDim.y;

    load_w_tile(Wt1, Wih, h0);
    load_w_tile(Wt2, Whh, h0);

    const int bA = b0 + ty2, bB = bA + 1;
    const int hX = h0 + tx2, hY = hX + 1;

    const float e0 = bih[hX] + bhh[hX];
    const float e1 = bih[hY] + bhh[hY];

    // zero our patch of hA (initial hidden state for layer 1)
    hA[(size_t)bA * HID + hX] = 0.f;
    hA[(size_t)bA * HID + hY] = 0.f;
    hA[(size_t)bB * HID + hX] = 0.f;
    hA[(size_t)bB * HID + hY] = 0.f;

    grid_barrier(nblocks);

    const size_t SEQS = (size_t)SEQ * HID;

    for (int t = 0; t < SEQ; t++) {
        const float* hprev = (t & 1) ? hB : hA;
        float*       hnext = (t & 1) ? hA : hB;
        const float* a0src = h1s + (size_t)t * HID;   // row stride SEQS (read-only)

        float c00 = 0.f, c01 = 0.f, c10 = 0.f, c11 = 0.f;

        #pragma unroll 1
        for (int kc = 0; kc < HID; kc += KC) {        // source 0: h1_t @ Wih^T
            stage_a_chunk(Asm, a0src, (long long)SEQS, b0, kc);
            __syncthreads();
            mm_chunk(Wt1, Asm, kc, tx2, ty2, c00, c01, c10, c11);
            __syncthreads();
        }
        #pragma unroll 1
        for (int kc = 0; kc < HID; kc += KC) {        // source 1: h_prev @ Whh^T
            stage_a_chunk_cg(Asm, hprev, HID, b0, kc);
            __syncthreads();
            mm_chunk(Wt2, Asm, kc, tx2, ty2, c00, c01, c10, c11);
            __syncthreads();
        }

        float v00 = tanhf(c00 + e0);
        float v01 = tanhf(c01 + e1);
        float v10 = tanhf(c10 + e0);
        float v11 = tanhf(c11 + e1);

        hnext[(size_t)bA * HID + hX] = v00;
        hnext[(size_t)bA * HID + hY] = v01;
        hnext[(size_t)bB * HID + hX] = v10;
        hnext[(size_t)bB * HID + hY] = v11;

        grid_barrier(nblocks);
    }
}

// ---------------------------------------------------------------------------
__global__ __launch_bounds__(128) void fc_kernel(
    const float* __restrict__ h, const float* __restrict__ Wfc,
    const float* __restrict__ bfc, float* __restrict__ out)
{
    const int b = blockIdx.x;
    const int tid = threadIdx.x;
    float s = 0.f;
    for (int k = tid; k < HID; k += 128)
        s = fmaf(h[(size_t)b * HID + k], Wfc[k], s);
    #pragma unroll
    for (int o = 16; o > 0; o >>= 1) s += __shfl_xor_sync(0xffffffffu, s, o);
    __shared__ float red[4];
    if ((tid & 31) == 0) red[tid >> 5] = s;
    __syncthreads();
    if (tid == 0) out[b] = red[0] + red[1] + red[2] + red[3] + bfc[0];
}

// ---------------------------------------------------------------------------
extern "C" void kernel_launch(void* const* d_in, const int* in_sizes, int n_in,
                              void* d_out, int out_size)
{
    const float* x    = (const float*)d_in[0];
    const float* Wih0 = (const float*)d_in[1];
    const float* Whh0 = (const float*)d_in[2];
    const float* bih0 = (const float*)d_in[3];
    const float* bhh0 = (const float*)d_in[4];
    const float* Wih1 = (const float*)d_in[5];
    const float* Whh1 = (const float*)d_in[6];
    const float* bih1 = (const float*)d_in[7];
    const float* bhh1 = (const float*)d_in[8];
    const float* Wfc  = (const float*)d_in[9];
    const float* bfc  = (const float*)d_in[10];
    float* out = (float*)d_out;

    float *seq0, *h1s, *hA, *hB;
    cudaGetSymbolAddress((void**)&seq0, g_seq0);
    cudaGetSymbolAddress((void**)&h1s,  g_h1);
    cudaGetSymbolAddress((void**)&hA,   g_hA);
    cudaGetSymbolAddress((void**)&hB,   g_hB);

    const int smem0 = (HID + KC) * PAD * sizeof(float);          //  ~76 KB
    const int smem1 = (2 * HID + KC) * PAD * sizeof(float);      // ~144 KB
    cudaFuncSetAttribute(rnn_layer0_persistent,
                         cudaFuncAttributeMaxDynamicSharedMemorySize, smem0);
    cudaFuncSetAttribute(rnn_layer1_persistent,
                         cudaFuncAttributeMaxDynamicSharedMemorySize, smem1);

    const dim3 sgrid(HID / 32, BATCH / 32);  // (16, 8) = 128 CTAs, co-resident on 148 SMs

    xp0_kernel<<<(BATCH * SEQ) / 16, 256>>>(x, Wih0, bih0, bhh0, seq0);
    rnn_layer0_persistent<<<sgrid, 256, smem0>>>(Whh0, seq0, h1s, hA, hB);
    rnn_layer1_persistent<<<sgrid, 256, smem1>>>(Wih1, Whh1, bih1, bhh1, h1s, hA, hB);
    // SEQ-1 = 511 is odd -> final state in hA
    fc_kernel<<<BATCH, 128>>>(hA, Wfc, bfc, out);

    (void)in_sizes; (void)n_in; (void)out_size;
}

// round 7
// speedup vs baseline: 1.2916x; 1.2835x over previous
#include <cuda_runtime.h>
#include <math.h>

#define BATCH 256
#define SEQ   512
#define INPUT 64
#define HID   512
#define KC    128          // k-chunk per staging buffer
#define WSTR  34           // transposed-W row stride (even -> float2-aligned; 34%32==2 -> conflict-free)
#define ASTR  132          // row-major A stride (mult of 4 -> float4-aligned STS.128)

// -------- scratch (static device globals; no allocations anywhere) --------
__device__ float g_seq0[(size_t)BATCH * SEQ * HID];  // xp0 (b, t, h)
__device__ float g_h1[(size_t)BATCH * SEQ * HID];    // layer-0 hidden states (b, t, h)
__device__ float g_hA[BATCH * HID];                  // ping
__device__ float g_hB[BATCH * HID];                  // pong
__device__ unsigned          g_bar_count;            // zero-initialized
__device__ volatile unsigned g_bar_gen;              // zero-initialized

// ---------------------------------------------------------------------------
// Software grid barrier (all 128 CTAs co-resident; proven in R6).
__device__ __forceinline__ void grid_barrier(unsigned nblocks) {
    __syncthreads();
    if (threadIdx.x == 0) {
        unsigned gen = g_bar_gen;
        __threadfence();
        unsigned arrived = atomicAdd(&g_bar_count, 1u);
        if (arrived == nblocks - 1u) {
            *(volatile unsigned*)&g_bar_count = 0u;
            __threadfence();
            g_bar_gen = gen + 1u;
        } else {
            while (g_bar_gen == gen) { }
            __threadfence();
        }
    }
    __syncthreads();
}

// ---------------------------------------------------------------------------
// xp0[bt][h] = sum_d x[bt][d] * Wih[h][d] + bih[h] + bhh[h]   (unchanged, proven)
__global__ __launch_bounds__(256) void xp0_kernel(
    const float* __restrict__ x, const float* __restrict__ Wih,
    const float* __restrict__ bih, const float* __restrict__ bhh,
    float* __restrict__ out)
{
    __shared__ float xs[16][INPUT];
    const int bt0 = blockIdx.x * 16;
    const int tid = threadIdx.x;
    {
        int r  = tid >> 4;
        int c4 = (tid & 15) * 4;
        float4 v = *reinterpret_cast<const float4*>(&x[(size_t)(bt0 + r) * INPUT + c4]);
        xs[r][c4 + 0] = v.x; xs[r][c4 + 1] = v.y;
        xs[r][c4 + 2] = v.z; xs[r][c4 + 3] = v.w;
    }
    __syncthreads();

    #pragma unroll
    for (int hh = 0; hh < 2; hh++) {
        const int h = tid + hh * 256;
        const float bias = bih[h] + bhh[h];
        float acc[16];
        #pragma unroll
        for (int r = 0; r < 16; r++) acc[r] = 0.0f;
        const float4* wrow = reinterpret_cast<const float4*>(&Wih[(size_t)h * INPUT]);
        #pragma unroll
        for (int k4 = 0; k4 < INPUT / 4; k4++) {
            float4 w = wrow[k4];
            #pragma unroll
            for (int r = 0; r < 16; r++) {
                float4 xv = *reinterpret_cast<const float4*>(&xs[r][k4 * 4]);
                acc[r] = fmaf(w.x, xv.x, acc[r]);
                acc[r] = fmaf(w.y, xv.y, acc[r]);
                acc[r] = fmaf(w.z, xv.z, acc[r]);
                acc[r] = fmaf(w.w, xv.w, acc[r]);
            }
        }
        #pragma unroll
        for (int r = 0; r < 16; r++)
            out[(size_t)(bt0 + r) * HID + h] = acc[r] + bias;
    }
}

// ---------------------------------------------------------------------------
// Build transposed W tile in smem (one time): Wt[k*WSTR + r] = W[(h0+r)*HID + k]
__device__ __forceinline__ void build_wt(float* Wt, const float* __restrict__ W, int h0) {
    const int r = threadIdx.x & 31;
    #pragma unroll 1
    for (int k = (threadIdx.x >> 5); k < HID; k += 8)
        Wt[k * WSTR + r] = W[(size_t)(h0 + r) * HID + k];
}

// ---------------------------------------------------------------------------
// Double-buffered A staging: row-major [32][ASTR], coalesced LDG.128 (L1 bypass)
struct StageRegs { float4 v[4]; };

__device__ __forceinline__ void stage_load(StageRegs& s, const float* __restrict__ A,
                                           long long astr, int b0, int kc) {
    const int r = threadIdx.x >> 3;           // 0..31
    const int c = (threadIdx.x & 7) * 16;     // 0,16,...,112
    const float* base = A + (size_t)(b0 + r) * astr + kc + c;
    #pragma unroll
    for (int j = 0; j < 4; j++)
        s.v[j] = __ldcg(reinterpret_cast<const float4*>(base + 4 * j));
}

__device__ __forceinline__ void stage_store(const StageRegs& s, float* As) {
    const int r = threadIdx.x >> 3;
    const int c = (threadIdx.x & 7) * 16;
    float* dst = As + r * ASTR + c;
    #pragma unroll
    for (int j = 0; j < 4; j++)
        *reinterpret_cast<float4*>(dst + 4 * j) = s.v[j];
}

// ---------------------------------------------------------------------------
// Compute one KC-chunk: k-pair inner loop, float2 loads (4 crossbar phases / 2k / warp)
__device__ __forceinline__ void mm_chunk(const float* __restrict__ Wt_kc,  // Wt + kc*WSTR
                                         const float* __restrict__ As,
                                         int tx2, int ty2,
                                         float& c00, float& c01, float& c10, float& c11) {
    const float* a0p = As + ty2 * ASTR;
    const float* a1p = As + (ty2 + 1) * ASTR;
    const float* wp  = Wt_kc + tx2;
    #pragma unroll 16
    for (int kp = 0; kp < KC / 2; kp++) {
        float2 aA = *reinterpret_cast<const float2*>(a0p + 2 * kp);
        float2 aB = *reinterpret_cast<const float2*>(a1p + 2 * kp);
        float2 w0 = *reinterpret_cast<const float2*>(wp + (2 * kp) * WSTR);
        float2 w1 = *reinterpret_cast<const float2*>(wp + (2 * kp + 1) * WSTR);
        c00 = fmaf(aA.x, w0.x, c00); c00 = fmaf(aA.y, w1.x, c00);
        c01 = fmaf(aA.x, w0.y, c01); c01 = fmaf(aA.y, w1.y, c01);
        c10 = fmaf(aB.x, w0.x, c10); c10 = fmaf(aB.y, w1.x, c10);
        c11 = fmaf(aB.x, w0.y, c11); c11 = fmaf(aB.y, w1.y, c11);
    }
}

// ---------------------------------------------------------------------------
// Persistent layer-0. grid (16,8) = 128 CTAs x 256 threads.
// smem: Wt [HID*WSTR] + As[2][32*ASTR]
__global__ __launch_bounds__(256) void rnn_layer0_persistent(
    const float* __restrict__ Whh,
    const float* __restrict__ xp,    // (b, t, h), biases folded in
    float* __restrict__ h1s,         // (b, t, h)
    float* __restrict__ hA, float* __restrict__ hB)
{
    extern __shared__ float smem[];
    float* Wt  = smem;                       // HID*WSTR
    float* As0 = smem + HID * WSTR;          // 32*ASTR
    float* As1 = As0 + 32 * ASTR;

    const int tid = threadIdx.x;
    const int tx2 = (tid & 15) * 2;
    const int ty2 = (tid >> 4) * 2;
    const int h0  = blockIdx.x * 32;
    const int b0  = blockIdx.y * 32;
    const unsigned nblocks = gridDim.x * gridDim.y;

    build_wt(Wt, Whh, h0);

    const int bA = b0 + ty2, bB = bA + 1;
    const int hX = h0 + tx2, hY = hX + 1;

    // zero initial hidden state patch
    hA[(size_t)bA * HID + hX] = 0.f; hA[(size_t)bA * HID + hY] = 0.f;
    hA[(size_t)bB * HID + hX] = 0.f; hA[(size_t)bB * HID + hY] = 0.f;

    grid_barrier(nblocks);

    const size_t SEQS = (size_t)SEQ * HID;

    for (int t = 0; t < SEQ; t++) {
        const float* hprev = (t & 1) ? hB : hA;
        float*       hnext = (t & 1) ? hA : hB;

        // prefetch xp for this step (consumed only in the epilogue)
        const float* xpt = xp + (size_t)t * HID;
        float p00 = __ldg(&xpt[(size_t)bA * SEQS + hX]);
        float p01 = __ldg(&xpt[(size_t)bA * SEQS + hY]);
        float p10 = __ldg(&xpt[(size_t)bB * SEQS + hX]);
        float p11 = __ldg(&xpt[(size_t)bB * SEQS + hY]);

        StageRegs sr;
        stage_load(sr, hprev, HID, b0, 0);

        float c00 = 0.f, c01 = 0.f, c10 = 0.f, c11 = 0.f;
        #pragma unroll
        for (int ch = 0; ch < HID / KC; ch++) {          // 4 chunks
            float* buf = (ch & 1) ? As1 : As0;
            stage_store(sr, buf);
            __syncthreads();                              // one sync per chunk
            if (ch + 1 < HID / KC)
                stage_load(sr, hprev, HID, b0, (ch + 1) * KC);  // overlap with compute
            mm_chunk(Wt + ch * KC * WSTR, buf, tx2, ty2, c00, c01, c10, c11);
        }

        float v00 = tanhf(c00 + p00);
        float v01 = tanhf(c01 + p01);
        float v10 = tanhf(c10 + p10);
        float v11 = tanhf(c11 + p11);

        hnext[(size_t)bA * HID + hX] = v00;
        hnext[(size_t)bA * HID + hY] = v01;
        hnext[(size_t)bB * HID + hX] = v10;
        hnext[(size_t)bB * HID + hY] = v11;

        float* h1t = h1s + (size_t)t * HID;
        h1t[(size_t)bA * SEQS + hX] = v00;
        h1t[(size_t)bA * SEQS + hY] = v01;
        h1t[(size_t)bB * SEQS + hX] = v10;
        h1t[(size_t)bB * SEQS + hY] = v11;

        grid_barrier(nblocks);
    }
}

// ---------------------------------------------------------------------------
// Persistent layer-1: fused input GEMM (source 0: h1_t @ Wih^T; source 1: h_prev @ Whh^T)
// smem: Wt1 + Wt2 + As[2]  (~169 KB)
__global__ __launch_bounds__(256) void rnn_layer1_persistent(
    const float* __restrict__ Wih, const float* __restrict__ Whh,
    const float* __restrict__ bih, const float* __restrict__ bhh,
    const float* __restrict__ h1s, // (b, t, h)
    float* __restrict__ hA, float* __restrict__ hB)
{
    extern __shared__ float smem[];
    float* Wt1 = smem;                         // HID*WSTR
    float* Wt2 = smem + HID * WSTR;            // HID*WSTR
    float* As0 = smem + 2 * HID * WSTR;
    float* As1 = As0 + 32 * ASTR;

    const int tid = threadIdx.x;
    const int tx2 = (tid & 15) * 2;
    const int ty2 = (tid >> 4) * 2;
    const int h0  = blockIdx.x * 32;
    const int b0  = blockIdx.y * 32;
    const unsigned nblocks = gridDim.x * gridDim.y;

    build_wt(Wt1, Wih, h0);
    build_wt(Wt2, Whh, h0);

    const int bA = b0 + ty2, bB = bA + 1;
    const int hX = h0 + tx2, hY = hX + 1;

    const float e0 = bih[hX] + bhh[hX];
    const float e1 = bih[hY] + bhh[hY];

    hA[(size_t)bA * HID + hX] = 0.f; hA[(size_t)bA * HID + hY] = 0.f;
    hA[(size_t)bB * HID + hX] = 0.f; hA[(size_t)bB * HID + hY] = 0.f;

    grid_barrier(nblocks);

    const size_t SEQS = (size_t)SEQ * HID;
    const int NCH = 2 * (HID / KC);            // 8 chunks total

    for (int t = 0; t < SEQ; t++) {
        const float* hprev = (t & 1) ? hB : hA;
        float*       hnext = (t & 1) ? hA : hB;
        const float* a0src = h1s + (size_t)t * HID;   // row stride SEQS

        StageRegs sr;
        stage_load(sr, a0src, (long long)SEQS, b0, 0);

        float c00 = 0.f, c01 = 0.f, c10 = 0.f, c11 = 0.f;
        #pragma unroll
        for (int ch = 0; ch < NCH; ch++) {
            float* buf = (ch & 1) ? As1 : As0;
            stage_store(sr, buf);
            __syncthreads();
            if (ch + 1 < NCH) {
                int nx = ch + 1;
                const float*  nA   = (nx < HID / KC) ? a0src : hprev;
                long long     nstr = (nx < HID / KC) ? (long long)SEQS : (long long)HID;
                int           nkc  = (nx & (HID / KC - 1)) * KC;
                stage_load(sr, nA, nstr, b0, nkc);
            }
            const float* Wt_kc = ((ch < HID / KC) ? Wt1 : Wt2) + (ch & (HID / KC - 1)) * KC * WSTR;
            mm_chunk(Wt_kc, buf, tx2, ty2, c00, c01, c10, c11);
        }

        float v00 = tanhf(c00 + e0);
        float v01 = tanhf(c01 + e1);
        float v10 = tanhf(c10 + e0);
        float v11 = tanhf(c11 + e1);

        hnext[(size_t)bA * HID + hX] = v00;
        hnext[(size_t)bA * HID + hY] = v01;
        hnext[(size_t)bB * HID + hX] = v10;
        hnext[(size_t)bB * HID + hY] = v11;

        grid_barrier(nblocks);
    }
}

// ---------------------------------------------------------------------------
__global__ __launch_bounds__(128) void fc_kernel(
    const float* __restrict__ h, const float* __restrict__ Wfc,
    const float* __restrict__ bfc, float* __restrict__ out)
{
    const int b = blockIdx.x;
    const int tid = threadIdx.x;
    float s = 0.f;
    for (int k = tid; k < HID; k += 128)
        s = fmaf(h[(size_t)b * HID + k], Wfc[k], s);
    #pragma unroll
    for (int o = 16; o > 0; o >>= 1) s += __shfl_xor_sync(0xffffffffu, s, o);
    __shared__ float red[4];
    if ((tid & 31) == 0) red[tid >> 5] = s;
    __syncthreads();
    if (tid == 0) out[b] = red[0] + red[1] + red[2] + red[3] + bfc[0];
}

// ---------------------------------------------------------------------------
extern "C" void kernel_launch(void* const* d_in, const int* in_sizes, int n_in,
                              void* d_out, int out_size)
{
    const float* x    = (const float*)d_in[0];
    const float* Wih0 = (const float*)d_in[1];
    const float* Whh0 = (const float*)d_in[2];
    const float* bih0 = (const float*)d_in[3];
    const float* bhh0 = (const float*)d_in[4];
    const float* Wih1 = (const float*)d_in[5];
    const float* Whh1 = (const float*)d_in[6];
    const float* bih1 = (const float*)d_in[7];
    const float* bhh1 = (const float*)d_in[8];
    const float* Wfc  = (const float*)d_in[9];
    const float* bfc  = (const float*)d_in[10];
    float* out = (float*)d_out;

    float *seq0, *h1s, *hA, *hB;
    cudaGetSymbolAddress((void**)&seq0, g_seq0);
    cudaGetSymbolAddress((void**)&h1s,  g_h1);
    cudaGetSymbolAddress((void**)&hA,   g_hA);
    cudaGetSymbolAddress((void**)&hB,   g_hB);

    const int smem0 = (HID * WSTR + 2 * 32 * ASTR) * sizeof(float);      // ~101 KB
    const int smem1 = (2 * HID * WSTR + 2 * 32 * ASTR) * sizeof(float);  // ~169 KB
    cudaFuncSetAttribute(rnn_layer0_persistent,
                         cudaFuncAttributeMaxDynamicSharedMemorySize, smem0);
    cudaFuncSetAttribute(rnn_layer1_persistent,
                         cudaFuncAttributeMaxDynamicSharedMemorySize, smem1);

    const dim3 sgrid(HID / 32, BATCH / 32);  // (16, 8) = 128 co-resident CTAs

    xp0_kernel<<<(BATCH * SEQ) / 16, 256>>>(x, Wih0, bih0, bhh0, seq0);
    rnn_layer0_persistent<<<sgrid, 256, smem0>>>(Whh0, seq0, h1s, hA, hB);
    rnn_layer1_persistent<<<sgrid, 256, smem1>>>(Wih1, Whh1, bih1, bhh1, h1s, hA, hB);
    // SEQ-1 = 511 is odd -> final state in hA
    fc_kernel<<<BATCH, 128>>>(hA, Wfc, bfc, out);

    (void)in_sizes; (void)n_in; (void)out_size;
}

// round 8
// speedup vs baseline: 1.3555x; 1.0495x over previous
#include <cuda_runtime.h>
#include <math.h>

#define BATCH 256
#define SEQ   512
#define INPUT 64
#define HID   512
#define KC    128
#define ASTR  132   // A staging row stride (floats), mult of 4 for float4

typedef unsigned long long ull;

// -------- scratch (static device globals; no allocations anywhere) --------
__device__ float g_seq0[(size_t)BATCH * SEQ * HID];  // xp0 (b, t, h)
__device__ float g_h0A[BATCH * HID];   // layer-0 state ping
__device__ float g_h0B[BATCH * HID];   // layer-0 state pong
__device__ float g_h1A[BATCH * HID];   // layer-1 state ping
__device__ float g_h1B[BATCH * HID];   // layer-1 state pong
__device__ float g_hx0[BATCH * HID];   // L0->L1 handoff ping
__device__ float g_hx1[BATCH * HID];   // L0->L1 handoff pong
__device__ unsigned          g_bar_count;
__device__ volatile unsigned g_bar_gen;

// ---------------------------------------------------------------------------
__device__ __forceinline__ void grid_barrier(unsigned nblocks) {
    __syncthreads();
    if (threadIdx.x == 0) {
        unsigned gen = g_bar_gen;
        __threadfence();
        unsigned arrived = atomicAdd(&g_bar_count, 1u);
        if (arrived == nblocks - 1u) {
            *(volatile unsigned*)&g_bar_count = 0u;
            __threadfence();
            g_bar_gen = gen + 1u;
        } else {
            while (g_bar_gen == gen) { }
            __threadfence();
        }
    }
    __syncthreads();
}

// ---- packed f32x2 helpers (sm_10x): lane-wise IEEE fp32 FMA --------------
__device__ __forceinline__ ull dup_f32(float a) {
    ull d;
    asm("mov.b64 %0, {%1, %1};" : "=l"(d) : "f"(a));
    return d;
}
__device__ __forceinline__ void ffma2(ull& acc, ull a, ull b) {
    asm("fma.rn.f32x2 %0, %1, %2, %0;" : "+l"(acc) : "l"(a), "l"(b));
}
__device__ __forceinline__ void unpack2(ull v, float& lo, float& hi) {
    asm("mov.b64 {%0, %1}, %2;" : "=f"(lo), "=f"(hi) : "l"(v));
}

// ---------------------------------------------------------------------------
// xp0[bt][h] = sum_d x[bt][d] * Wih[h][d] + bih[h] + bhh[h]   (proven)
__global__ __launch_bounds__(256) void xp0_kernel(
    const float* __restrict__ x, const float* __restrict__ Wih,
    const float* __restrict__ bih, const float* __restrict__ bhh,
    float* __restrict__ out)
{
    __shared__ float xs[16][INPUT];
    const int bt0 = blockIdx.x * 16;
    const int tid = threadIdx.x;
    {
        int r  = tid >> 4;
        int c4 = (tid & 15) * 4;
        float4 v = *reinterpret_cast<const float4*>(&x[(size_t)(bt0 + r) * INPUT + c4]);
        xs[r][c4 + 0] = v.x; xs[r][c4 + 1] = v.y;
        xs[r][c4 + 2] = v.z; xs[r][c4 + 3] = v.w;
    }
    __syncthreads();

    #pragma unroll
    for (int hh = 0; hh < 2; hh++) {
        const int h = tid + hh * 256;
        const float bias = bih[h] + bhh[h];
        float acc[16];
        #pragma unroll
        for (int r = 0; r < 16; r++) acc[r] = 0.0f;
        const float4* wrow = reinterpret_cast<const float4*>(&Wih[(size_t)h * INPUT]);
        #pragma unroll
        for (int k4 = 0; k4 < INPUT / 4; k4++) {
            float4 w = wrow[k4];
            #pragma unroll
            for (int r = 0; r < 16; r++) {
                float4 xv = *reinterpret_cast<const float4*>(&xs[r][k4 * 4]);
                acc[r] = fmaf(w.x, xv.x, acc[r]);
                acc[r] = fmaf(w.y, xv.y, acc[r]);
                acc[r] = fmaf(w.z, xv.z, acc[r]);
                acc[r] = fmaf(w.w, xv.w, acc[r]);
            }
        }
        #pragma unroll
        for (int r = 0; r < 16; r++)
            out[(size_t)(bt0 + r) * HID + h] = acc[r] + bias;
    }
}

// ---------------------------------------------------------------------------
// Packed W tile (one-time build). For k-pair p (k=2p,2p+1) and h-pair j:
//   WqF[(p*16+j)*4 + {0,1,2,3}] = { W[2p][hX], W[2p][hY], W[2p+1][hX], W[2p+1][hY] }
// where hX = h0+2j, hY = hX+1. 256 p * 16 j * 4 = 16384 floats = 64 KB dense.
__device__ __forceinline__ void build_wq(float* WqF, const float* __restrict__ W, int h0) {
    const int tid = threadIdx.x;
    const int j = tid & 15;
    const int hX = h0 + 2 * j, hY = hX + 1;
    #pragma unroll 1
    for (int p = tid >> 4; p < HID / 2; p += 16) {
        float w00 = __ldg(&W[(size_t)hX * HID + 2 * p]);
        float w10 = __ldg(&W[(size_t)hY * HID + 2 * p]);
        float w01 = __ldg(&W[(size_t)hX * HID + 2 * p + 1]);
        float w11 = __ldg(&W[(size_t)hY * HID + 2 * p + 1]);
        *reinterpret_cast<float4*>(WqF + ((size_t)p * 16 + j) * 4) =
            make_float4(w00, w10, w01, w11);
    }
}

// ---------------------------------------------------------------------------
// A staging: 32 rows x KC cols, row-major stride ASTR. LDG.128 x4, L1-bypass.
struct StageRegs { float4 v[4]; };

__device__ __forceinline__ void stage_load(StageRegs& s, const float* __restrict__ A,
                                           int b0, int kc) {
    const int r = threadIdx.x >> 3;
    const int c = (threadIdx.x & 7) * 16;
    const float* base = A + (size_t)(b0 + r) * HID + kc + c;
    #pragma unroll
    for (int jj = 0; jj < 4; jj++)
        s.v[jj] = __ldcg(reinterpret_cast<const float4*>(base + 4 * jj));
}
__device__ __forceinline__ void stage_store(const StageRegs& s, float* As) {
    const int r = threadIdx.x >> 3;
    const int c = (threadIdx.x & 7) * 16;
    float* dst = As + r * ASTR + c;
    #pragma unroll
    for (int jj = 0; jj < 4; jj++)
        *reinterpret_cast<float4*>(dst + 4 * jj) = s.v[jj];
}

// ---------------------------------------------------------------------------
// One KC chunk with packed FFMA2. wq points at this chunk's ulonglong2 base.
// acc0 = (c[bA][hX], c[bA][hY]),  acc1 = (c[bB][hX], c[bB][hY])
__device__ __forceinline__ void mm_chunk2(
    const ulonglong2* __restrict__ wq, const float* __restrict__ As,
    int tx, int ty2, ull& acc0, ull& acc1)
{
    const float* a0p = As + ty2 * ASTR;
    const float* a1p = a0p + ASTR;
    #pragma unroll
    for (int q = 0; q < KC / 4; q++) {
        float4 aA = *reinterpret_cast<const float4*>(a0p + 4 * q);
        float4 aB = *reinterpret_cast<const float4*>(a1p + 4 * q);
        ulonglong2 w0 = wq[(2 * q) * 16 + tx];       // k = 4q, 4q+1
        ulonglong2 w1 = wq[(2 * q + 1) * 16 + tx];   // k = 4q+2, 4q+3
        ffma2(acc0, dup_f32(aA.x), w0.x);  ffma2(acc1, dup_f32(aB.x), w0.x);
        ffma2(acc0, dup_f32(aA.y), w0.y);  ffma2(acc1, dup_f32(aB.y), w0.y);
        ffma2(acc0, dup_f32(aA.z), w1.x);  ffma2(acc1, dup_f32(aB.z), w1.x);
        ffma2(acc0, dup_f32(aA.w), w1.y);  ffma2(acc1, dup_f32(aB.w), w1.y);
    }
}

// ---------------------------------------------------------------------------
// Fused wavefront persistent kernel: superstep t does L0 step t and L1 step t-1.
// grid (16, 8) = 128 CTAs x 256 threads; smem = 3 W tiles (192KB) + A staging (33KB).
__global__ __launch_bounds__(256) void rnn_fused_persistent(
    const float* __restrict__ Whh0,
    const float* __restrict__ Wih1, const float* __restrict__ Whh1,
    const float* __restrict__ bih1, const float* __restrict__ bhh1,
    const float* __restrict__ xp)
{
    extern __shared__ float smem[];
    float* Wq0 = smem;                 // 16384 floats
    float* Wq1 = smem + 16384;         // Wih1
    float* Wq2 = smem + 32768;         // Whh1
    float* As0 = smem + 49152;         // 32*ASTR
    float* As1 = As0 + 32 * ASTR;

    const int tid = threadIdx.x;
    const int tx  = tid & 15;
    const int ty2 = (tid >> 4) * 2;
    const int h0  = blockIdx.x * 32;
    const int b0  = blockIdx.y * 32;
    const unsigned nblocks = gridDim.x * gridDim.y;

    build_wq(Wq0, Whh0, h0);
    build_wq(Wq1, Wih1, h0);
    build_wq(Wq2, Whh1, h0);

    const int bA = b0 + ty2, bB = bA + 1;
    const int hX = h0 + 2 * tx, hY = hX + 1;

    const float e0 = bih1[hX] + bhh1[hX];
    const float e1 = bih1[hY] + bhh1[hY];

    // zero initial states (our patch)
    g_h0A[(size_t)bA * HID + hX] = 0.f; g_h0A[(size_t)bA * HID + hY] = 0.f;
    g_h0A[(size_t)bB * HID + hX] = 0.f; g_h0A[(size_t)bB * HID + hY] = 0.f;
    g_h1A[(size_t)bA * HID + hX] = 0.f; g_h1A[(size_t)bA * HID + hY] = 0.f;
    g_h1A[(size_t)bB * HID + hX] = 0.f; g_h1A[(size_t)bB * HID + hY] = 0.f;

    grid_barrier(nblocks);

    const size_t SEQS = (size_t)SEQ * HID;

    for (int t = 0; t <= SEQ; t++) {
        // ---------------- layer 0, step t ----------------
        if (t < SEQ) {
            const float* hprev0 = (t & 1) ? g_h0B : g_h0A;
            float*       hnext0 = (t & 1) ? g_h0A : g_h0B;
            float*       hxout  = (t & 1) ? g_hx1 : g_hx0;

            const float* xpt = xp + (size_t)t * HID;
            float p00 = __ldg(&xpt[(size_t)bA * SEQS + hX]);
            float p01 = __ldg(&xpt[(size_t)bA * SEQS + hY]);
            float p10 = __ldg(&xpt[(size_t)bB * SEQS + hX]);
            float p11 = __ldg(&xpt[(size_t)bB * SEQS + hY]);

            StageRegs sr;
            stage_load(sr, hprev0, b0, 0);
            ull acc0 = 0ull, acc1 = 0ull;
            #pragma unroll 1
            for (int ch = 0; ch < HID / KC; ch++) {       // 4 chunks
                float* buf = (ch & 1) ? As1 : As0;
                stage_store(sr, buf);
                __syncthreads();
                if (ch + 1 < HID / KC) stage_load(sr, hprev0, b0, (ch + 1) * KC);
                mm_chunk2(reinterpret_cast<const ulonglong2*>(Wq0) + (size_t)ch * 1024,
                          buf, tx, ty2, acc0, acc1);
            }
            float c00, c01, c10, c11;
            unpack2(acc0, c00, c01);
            unpack2(acc1, c10, c11);
            float v00 = tanhf(c00 + p00);
            float v01 = tanhf(c01 + p01);
            float v10 = tanhf(c10 + p10);
            float v11 = tanhf(c11 + p11);
            hnext0[(size_t)bA * HID + hX] = v00; hnext0[(size_t)bA * HID + hY] = v01;
            hnext0[(size_t)bB * HID + hX] = v10; hnext0[(size_t)bB * HID + hY] = v11;
            hxout[(size_t)bA * HID + hX]  = v00; hxout[(size_t)bA * HID + hY]  = v01;
            hxout[(size_t)bB * HID + hX]  = v10; hxout[(size_t)bB * HID + hY]  = v11;
        }

        // ---------------- layer 1, step s = t-1 ----------------
        if (t > 0) {
            const int s = t - 1;
            const float* h1in   = (s & 1) ? g_hx1 : g_hx0;   // L0 output of step s
            const float* hprev1 = (s & 1) ? g_h1B : g_h1A;
            float*       hnext1 = (s & 1) ? g_h1A : g_h1B;

            StageRegs sr;
            stage_load(sr, h1in, b0, 0);
            ull acc0 = 0ull, acc1 = 0ull;
            #pragma unroll 1
            for (int ch = 0; ch < 2 * (HID / KC); ch++) {  // 8 chunks
                float* buf = (ch & 1) ? As1 : As0;
                stage_store(sr, buf);
                __syncthreads();
                if (ch + 1 < 2 * (HID / KC)) {
                    int nx = ch + 1;
                    const float* nA = (nx < HID / KC) ? h1in : hprev1;
                    stage_load(sr, nA, b0, (nx & (HID / KC - 1)) * KC);
                }
                const float* WqF = (ch < HID / KC) ? Wq1 : Wq2;
                mm_chunk2(reinterpret_cast<const ulonglong2*>(WqF)
                              + (size_t)(ch & (HID / KC - 1)) * 1024,
                          buf, tx, ty2, acc0, acc1);
            }
            float c00, c01, c10, c11;
            unpack2(acc0, c00, c01);
            unpack2(acc1, c10, c11);
            float v00 = tanhf(c00 + e0);
            float v01 = tanhf(c01 + e1);
            float v10 = tanhf(c10 + e0);
            float v11 = tanhf(c11 + e1);
            hnext1[(size_t)bA * HID + hX] = v00; hnext1[(size_t)bA * HID + hY] = v01;
            hnext1[(size_t)bB * HID + hX] = v10; hnext1[(size_t)bB * HID + hY] = v11;
        }

        grid_barrier(nblocks);
    }
}

// ---------------------------------------------------------------------------
__global__ __launch_bounds__(128) void fc_kernel(
    const float* __restrict__ h, const float* __restrict__ Wfc,
    const float* __restrict__ bfc, float* __restrict__ out)
{
    const int b = blockIdx.x;
    const int tid = threadIdx.x;
    float s = 0.f;
    for (int k = tid; k < HID; k += 128)
        s = fmaf(h[(size_t)b * HID + k], Wfc[k], s);
    #pragma unroll
    for (int o = 16; o > 0; o >>= 1) s += __shfl_xor_sync(0xffffffffu, s, o);
    __shared__ float red[4];
    if ((tid & 31) == 0) red[tid >> 5] = s;
    __syncthreads();
    if (tid == 0) out[b] = red[0] + red[1] + red[2] + red[3] + bfc[0];
}

// ---------------------------------------------------------------------------
extern "C" void kernel_launch(void* const* d_in, const int* in_sizes, int n_in,
                              void* d_out, int out_size)
{
    const float* x    = (const float*)d_in[0];
    const float* Wih0 = (const float*)d_in[1];
    const float* Whh0 = (const float*)d_in[2];
    const float* bih0 = (const float*)d_in[3];
    const float* bhh0 = (const float*)d_in[4];
    const float* Wih1 = (const float*)d_in[5];
    const float* Whh1 = (const float*)d_in[6];
    const float* bih1 = (const float*)d_in[7];
    const float* bhh1 = (const float*)d_in[8];
    const float* Wfc  = (const float*)d_in[9];
    const float* bfc  = (const float*)d_in[10];
    float* out = (float*)d_out;

    float *seq0, *h1A;
    cudaGetSymbolAddress((void**)&seq0, g_seq0);
    cudaGetSymbolAddress((void**)&h1A,  g_h1A);

    const int smem_f = (3 * 16384 + 2 * 32 * ASTR) * sizeof(float);  // 230400 B
    cudaFuncSetAttribute(rnn_fused_persistent,
                         cudaFuncAttributeMaxDynamicSharedMemorySize, smem_f);

    const dim3 sgrid(HID / 32, BATCH / 32);  // (16, 8) = 128 co-resident CTAs

    xp0_kernel<<<(BATCH * SEQ) / 16, 256>>>(x, Wih0, bih0, bhh0, seq0);
    rnn_fused_persistent<<<sgrid, 256, smem_f>>>(Whh0, Wih1, Whh1, bih1, bhh1, seq0);
    // L1 final step s = 511 (odd) -> state in g_h1A
    fc_kernel<<<BATCH, 128>>>(h1A, Wfc, bfc, out);

    (void)in_sizes; (void)n_in; (void)out_size;
}

// round 13
// speedup vs baseline: 1.9559x; 1.4430x over previous
#include <cuda_runtime.h>
#include <cuda_bf16.h>
#include <math.h>
#include <cstdint>

#define BATCH 256
#define SEQ   512
#define INPUT 64
#define HID   512
#define HSZ   (BATCH * HID)

// ---------------- scratch (device globals; no allocations) ------------------
__device__ float g_seq0[(size_t)BATCH * SEQ * HID];            // xp0 (b, t, h)
__device__ __nv_bfloat16 g_hxhi[2 * HSZ], g_hxlo[2 * HSZ];     // L0 state / handoff
__device__ __nv_bfloat16 g_h1hi[2 * HSZ], g_h1lo[2 * HSZ];     // L1 state
__device__ float g_h1f[2 * HSZ];                               // L1 state fp32 (FC)
__device__ __nv_bfloat16 g_W0hi[HID * HID], g_W0lo[HID * HID]; // Whh0
__device__ __nv_bfloat16 g_W1hi[HID * HID], g_W1lo[HID * HID]; // Wih1
__device__ __nv_bfloat16 g_W2hi[HID * HID], g_W2lo[HID * HID]; // Whh1
__device__ unsigned          g_bar_count;
__device__ volatile unsigned g_bar_gen;

// ---------------------------------------------------------------------------
__device__ __forceinline__ void grid_barrier(unsigned nblocks) {
    __syncthreads();
    if (threadIdx.x == 0) {
        unsigned gen = g_bar_gen;
        __threadfence();
        unsigned arrived = atomicAdd(&g_bar_count, 1u);
        if (arrived == nblocks - 1u) {
            *(volatile unsigned*)&g_bar_count = 0u;
            __threadfence();
            g_bar_gen = gen + 1u;
        } else {
            while (g_bar_gen == gen) { }
            __threadfence();
        }
    }
    __syncthreads();
}

__device__ __forceinline__ uint32_t smem_to_u32(const void* p) {
    uint32_t a;
    asm("{ .reg .u64 t; cvta.to.shared.u64 t, %1; cvt.u32.u64 %0, t; }" : "=r"(a) : "l"(p));
    return a;
}

// ---- warp MMA primitives (baseline PTX, sm_80+: compiles for plain sm_103) --
__device__ __forceinline__ void ldm_x4(uint32_t* r, uint32_t addr) {
    asm volatile("ldmatrix.sync.aligned.m8n8.x4.shared.b16 {%0,%1,%2,%3}, [%4];"
                 : "=r"(r[0]), "=r"(r[1]), "=r"(r[2]), "=r"(r[3]) : "r"(addr));
}
__device__ __forceinline__ void mma16816(float* d, const uint32_t* a, uint32_t b0, uint32_t b1) {
    asm volatile(
        "mma.sync.aligned.m16n8k16.row.col.f32.bf16.bf16.f32 "
        "{%0,%1,%2,%3}, {%4,%5,%6,%7}, {%8,%9}, {%0,%1,%2,%3};"
        : "+f"(d[0]), "+f"(d[1]), "+f"(d[2]), "+f"(d[3])
        : "r"(a[0]), "r"(a[1]), "r"(a[2]), "r"(a[3]), "r"(b0), "r"(b1));
}

// ---------------------------------------------------------------------------
// xp0 (proven)
__global__ __launch_bounds__(256) void xp0_kernel(
    const float* __restrict__ x, const float* __restrict__ Wih,
    const float* __restrict__ bih, const float* __restrict__ bhh,
    float* __restrict__ out)
{
    __shared__ float xs[16][INPUT];
    const int bt0 = blockIdx.x * 16;
    const int tid = threadIdx.x;
    {
        int r = tid >> 4, c4 = (tid & 15) * 4;
        float4 v = *reinterpret_cast<const float4*>(&x[(size_t)(bt0 + r) * INPUT + c4]);
        xs[r][c4 + 0] = v.x; xs[r][c4 + 1] = v.y; xs[r][c4 + 2] = v.z; xs[r][c4 + 3] = v.w;
    }
    __syncthreads();
    #pragma unroll
    for (int hh = 0; hh < 2; hh++) {
        const int h = tid + hh * 256;
        const float bias = bih[h] + bhh[h];
        float acc[16];
        #pragma unroll
        for (int r = 0; r < 16; r++) acc[r] = 0.0f;
        const float4* wrow = reinterpret_cast<const float4*>(&Wih[(size_t)h * INPUT]);
        #pragma unroll
        for (int k4 = 0; k4 < INPUT / 4; k4++) {
            float4 w = wrow[k4];
            #pragma unroll
            for (int r = 0; r < 16; r++) {
                float4 xv = *reinterpret_cast<const float4*>(&xs[r][k4 * 4]);
                acc[r] = fmaf(w.x, xv.x, acc[r]); acc[r] = fmaf(w.y, xv.y, acc[r]);
                acc[r] = fmaf(w.z, xv.z, acc[r]); acc[r] = fmaf(w.w, xv.w, acc[r]);
            }
        }
        #pragma unroll
        for (int r = 0; r < 16; r++)
            out[(size_t)(bt0 + r) * HID + h] = acc[r] + bias;
    }
}

// W fp32 -> (hi, lo) bf16
__global__ __launch_bounds__(256) void wconv_kernel(
    const float* __restrict__ W, __nv_bfloat16* __restrict__ hi,
    __nv_bfloat16* __restrict__ lo)
{
    int i = blockIdx.x * 256 + threadIdx.x;
    float w = W[i];
    __nv_bfloat16 h = __float2bfloat16(w);
    hi[i] = h;
    lo[i] = __float2bfloat16(w - __bfloat162float(h));
}

// ---------------------------------------------------------------------------
// smem layout (bytes). Chunks are [32 rows][128B] with granule swizzle g^(r&7).
#define SM_BIAS 0
#define SM_W    1024
#define W_BLOCK 4096
#define SM_A    (SM_W + 3 * 2 * 8 * W_BLOCK)     // 197632
#define SM_TOTAL (SM_A + 2 * 2 * 4096)           // 214016

// A-chunk staging registers (per thread: row tid>>2, granules tid&3 and +4)
struct SR { uint4 a, b, c, d; };

__device__ __forceinline__ void sr_load(SR& s, const __nv_bfloat16* __restrict__ hi,
                                        const __nv_bfloat16* __restrict__ lo,
                                        int b0, int kc) {
    const int r = threadIdx.x >> 2, g1 = threadIdx.x & 3, g2 = g1 + 4;
    const uint4* ph = reinterpret_cast<const uint4*>(hi + (size_t)(b0 + r) * HID + kc);
    const uint4* pl = reinterpret_cast<const uint4*>(lo + (size_t)(b0 + r) * HID + kc);
    s.a = __ldcg(ph + g1); s.b = __ldcg(ph + g2);
    s.c = __ldcg(pl + g1); s.d = __ldcg(pl + g2);
}
__device__ __forceinline__ void sr_store(const SR& s, char* abuf) {
    const int r = threadIdx.x >> 2, g1 = threadIdx.x & 3, g2 = g1 + 4;
    const int x = r & 7;
    *reinterpret_cast<uint4*>(abuf + r * 128 + ((g1 ^ x) * 16)) = s.a;
    *reinterpret_cast<uint4*>(abuf + r * 128 + ((g2 ^ x) * 16)) = s.b;
    *reinterpret_cast<uint4*>(abuf + 4096 + r * 128 + ((g1 ^ x) * 16)) = s.c;
    *reinterpret_cast<uint4*>(abuf + 4096 + r * 128 + ((g2 ^ x) * 16)) = s.d;
}

// One 64-k chunk: 16 ldmatrix.x4 + 24 HMMA per warp (3-term hi/lo split).
struct LaneAddr { int aOff, aXor, aKh, wOff, wXor, wKh; };

__device__ __forceinline__ void compute_chunk(
    uint32_t aHiB, uint32_t wHiB, const LaneAddr& L, float* accA, float* accB)
{
    #pragma unroll
    for (int j = 0; j < 4; j++) {
        uint32_t ahi[4], alo[4], whi[4], wlo[4];
        const uint32_t ga = (uint32_t)(((2 * j + L.aKh) ^ L.aXor) * 16);
        const uint32_t gw = (uint32_t)(((2 * j + L.wKh) ^ L.wXor) * 16);
        ldm_x4(ahi, aHiB + L.aOff + ga);
        ldm_x4(alo, aHiB + 4096 + L.aOff + ga);
        ldm_x4(whi, wHiB + L.wOff + gw);
        ldm_x4(wlo, wHiB + 8 * W_BLOCK + L.wOff + gw);
        mma16816(accA, ahi, whi[0], whi[1]);
        mma16816(accA, alo, whi[0], whi[1]);
        mma16816(accA, ahi, wlo[0], wlo[1]);
        mma16816(accB, ahi, whi[2], whi[3]);
        mma16816(accB, alo, whi[2], whi[3]);
        mma16816(accB, ahi, wlo[2], wlo[3]);
    }
}

// ---------------------------------------------------------------------------
// Persistent HMMA wavefront kernel. grid (16, 8) = 128 CTAs x 128 threads.
__global__ __launch_bounds__(128) void rnn_mma_persistent(
    const float* __restrict__ xp,
    const float* __restrict__ bih1, const float* __restrict__ bhh1)
{
    extern __shared__ char smem[];
    const uint32_t smem_base = smem_to_u32(smem);
    const int tid = threadIdx.x;
    const int h0  = blockIdx.x * 32;
    const int b0  = blockIdx.y * 32;
    const unsigned nblocks = gridDim.x * gridDim.y;

    // bias for L1 epilogue
    if (tid < 32)
        *reinterpret_cast<float*>(smem + SM_BIAS + tid * 4) = bih1[h0 + tid] + bhh1[h0 + tid];

    // ---- build resident W tiles (hi/lo x 3 matrices, swizzled 64-k chunks) ----
    {
        const int r = tid >> 2, g1 = tid & 3, g2 = g1 + 4;
        const int x = r & 7;
        #pragma unroll 1
        for (int mh = 0; mh < 6; mh++) {
            const __nv_bfloat16* src =
                (mh == 0) ? g_W0hi : (mh == 1) ? g_W0lo :
                (mh == 2) ? g_W1hi : (mh == 3) ? g_W1lo :
                (mh == 4) ? g_W2hi : g_W2lo;
            // mh = m*2+hl ; block index = mh*8 + c
            #pragma unroll 1
            for (int c = 0; c < 8; c++) {
                const uint4* gp = reinterpret_cast<const uint4*>(
                    src + (size_t)(h0 + r) * HID + c * 64);
                uint4 v1 = __ldg(gp + g1);
                uint4 v2 = __ldg(gp + g2);
                char* base = smem + SM_W + (size_t)(mh * 8 + c) * W_BLOCK;
                *reinterpret_cast<uint4*>(base + r * 128 + ((g1 ^ x) * 16)) = v1;
                *reinterpret_cast<uint4*>(base + r * 128 + ((g2 ^ x) * 16)) = v2;
            }
        }
    }

    // ---- zero initial parity-1 states ----
    {
        const int r = tid >> 2, cb = (tid & 3) * 8;
        const size_t o = (size_t)HSZ + (size_t)(b0 + r) * HID + h0 + cb;
        const uint4 z = make_uint4(0, 0, 0, 0);
        __stcg(reinterpret_cast<uint4*>(g_hxhi + o), z);
        __stcg(reinterpret_cast<uint4*>(g_hxlo + o), z);
        __stcg(reinterpret_cast<uint4*>(g_h1hi + o), z);
        __stcg(reinterpret_cast<uint4*>(g_h1lo + o), z);
    }
    __syncthreads();
    grid_barrier(nblocks);

    // per-lane fragment addressing constants
    const int warp = tid >> 5, lane = tid & 31;
    const int wm = warp & 1, wn = warp >> 1;
    LaneAddr L;
    {
        const int blk = lane >> 3, lr = lane & 7;
        const int aRow = wm * 16 + (blk & 1) * 8 + lr;
        const int wRow = wn * 16 + (blk >> 1) * 8 + lr;
        L.aOff = aRow * 128; L.aXor = aRow & 7; L.aKh = blk >> 1;
        L.wOff = wRow * 128; L.wXor = wRow & 7; L.wKh = blk & 1;
    }
    // epilogue coords
    const int erow = b0 + wm * 16 + (lane >> 2);
    const int ecol = h0 + wn * 16 + (lane & 3) * 2;

    const uint32_t aB0 = smem_base + SM_A;            // staging buf 0 (hi; lo = +4096)
    const uint32_t aB1 = smem_base + SM_A + 8192;     // staging buf 1

    for (int t = 0; t <= SEQ; t++) {
        const size_t l0in  = (size_t)((t + 1) & 1) * HSZ;
        const size_t l0out = (size_t)(t & 1) * HSZ;

        // prefetch L0 chunk 0 and L1 chunk 0 (both readable at superstep start)
        SR sr, sr1;
        if (t < SEQ) sr_load(sr, g_hxhi + l0in, g_hxlo + l0in, b0, 0);
        const int s = t - 1;
        const size_t xOff  = (size_t)(s & 1) * HSZ;
        const size_t l1in  = (size_t)((s + 1) & 1) * HSZ;
        const size_t l1out = (size_t)(s & 1) * HSZ;
        if (t > 0) sr_load(sr1, g_hxhi + xOff, g_hxlo + xOff, b0, 0);

        // ================= layer 0, step t =================
        if (t < SEQ) {
            float acc0[4] = {0, 0, 0, 0}, acc1[4] = {0, 0, 0, 0};
            #pragma unroll 1
            for (int c = 0; c < 8; c++) {
                char* abuf = smem + SM_A + (size_t)(c & 1) * 8192;
                sr_store(sr, abuf);
                __syncthreads();
                if (c + 1 < 8)
                    sr_load(sr, g_hxhi + l0in, g_hxlo + l0in, b0, (c + 1) * 64);
                compute_chunk((c & 1) ? aB1 : aB0,
                              smem_base + SM_W + (uint32_t)(0 * 16 + c) * W_BLOCK,
                              L, acc0, acc1);
            }
            // epilogue: + xp, tanh, hi/lo split, store
            #pragma unroll
            for (int tile = 0; tile < 2; tile++) {
                const int h = ecol + tile * 8;
                const float* ac = tile ? acc1 : acc0;
                #pragma unroll
                for (int half = 0; half < 2; half++) {
                    const int b = erow + half * 8;
                    const float2 xv = *reinterpret_cast<const float2*>(
                        &xp[((size_t)b * SEQ + t) * HID + h]);
                    float v0 = tanhf(ac[half * 2 + 0] + xv.x);
                    float v1 = tanhf(ac[half * 2 + 1] + xv.y);
                    __nv_bfloat162 hh = __float22bfloat162_rn(make_float2(v0, v1));
                    float r0 = v0 - __bfloat162float(hh.x);
                    float r1 = v1 - __bfloat162float(hh.y);
                    __nv_bfloat162 ll = __float22bfloat162_rn(make_float2(r0, r1));
                    const size_t o = l0out + (size_t)b * HID + h;
                    __stcg(reinterpret_cast<uint32_t*>(g_hxhi + o),
                           *reinterpret_cast<uint32_t*>(&hh));
                    __stcg(reinterpret_cast<uint32_t*>(g_hxlo + o),
                           *reinterpret_cast<uint32_t*>(&ll));
                }
            }
        }

        // ================= layer 1, step s = t-1 =================
        if (t > 0) {
            float acc0[4] = {0, 0, 0, 0}, acc1[4] = {0, 0, 0, 0};
            #pragma unroll 1
            for (int c = 0; c < 16; c++) {
                char* abuf = smem + SM_A + (size_t)(c & 1) * 8192;
                sr_store(sr1, abuf);
                __syncthreads();
                if (c + 1 < 16) {
                    const int nx = c + 1;
                    if (nx < 8)
                        sr_load(sr1, g_hxhi + xOff, g_hxlo + xOff, b0, nx * 64);
                    else
                        sr_load(sr1, g_h1hi + l1in, g_h1lo + l1in, b0, (nx - 8) * 64);
                }
                const int m = (c < 8) ? 1 : 2;
                compute_chunk((c & 1) ? aB1 : aB0,
                              smem_base + SM_W + (uint32_t)(m * 16 + (c & 7)) * W_BLOCK,
                              L, acc0, acc1);
            }
            // epilogue: + bias, tanh, hi/lo split + fp32 store
            #pragma unroll
            for (int tile = 0; tile < 2; tile++) {
                const int h = ecol + tile * 8;
                const float* ac = tile ? acc1 : acc0;
                const float2 ev = *reinterpret_cast<const float2*>(
                    smem + SM_BIAS + (h - h0) * 4);
                #pragma unroll
                for (int half = 0; half < 2; half++) {
                    const int b = erow + half * 8;
                    float v0 = tanhf(ac[half * 2 + 0] + ev.x);
                    float v1 = tanhf(ac[half * 2 + 1] + ev.y);
                    __nv_bfloat162 hh = __float22bfloat162_rn(make_float2(v0, v1));
                    float r0 = v0 - __bfloat162float(hh.x);
                    float r1 = v1 - __bfloat162float(hh.y);
                    __nv_bfloat162 ll = __float22bfloat162_rn(make_float2(r0, r1));
                    const size_t o = l1out + (size_t)b * HID + h;
                    __stcg(reinterpret_cast<uint32_t*>(g_h1hi + o),
                           *reinterpret_cast<uint32_t*>(&hh));
                    __stcg(reinterpret_cast<uint32_t*>(g_h1lo + o),
                           *reinterpret_cast<uint32_t*>(&ll));
                    __stcg(reinterpret_cast<float2*>(g_h1f + o), make_float2(v0, v1));
                }
            }
        }

        grid_barrier(nblocks);
    }
}

// ---------------------------------------------------------------------------
__global__ __launch_bounds__(128) void fc_kernel(
    const float* __restrict__ h, const float* __restrict__ Wfc,
    const float* __restrict__ bfc, float* __restrict__ out)
{
    const int bq = blockIdx.x;
    const int tid = threadIdx.x;
    float s = 0.f;
    for (int k = tid; k < HID; k += 128)
        s = fmaf(h[(size_t)bq * HID + k], Wfc[k], s);
    #pragma unroll
    for (int o = 16; o > 0; o >>= 1) s += __shfl_xor_sync(0xffffffffu, s, o);
    __shared__ float red[4];
    if ((tid & 31) == 0) red[tid >> 5] = s;
    __syncthreads();
    if (tid == 0) out[bq] = red[0] + red[1] + red[2] + red[3] + bfc[0];
}

// ---------------------------------------------------------------------------
extern "C" void kernel_launch(void* const* d_in, const int* in_sizes, int n_in,
                              void* d_out, int out_size)
{
    const float* x    = (const float*)d_in[0];
    const float* Wih0 = (const float*)d_in[1];
    const float* Whh0 = (const float*)d_in[2];
    const float* bih0 = (const float*)d_in[3];
    const float* bhh0 = (const float*)d_in[4];
    const float* Wih1 = (const float*)d_in[5];
    const float* Whh1 = (const float*)d_in[6];
    const float* bih1 = (const float*)d_in[7];
    const float* bhh1 = (const float*)d_in[8];
    const float* Wfc  = (const float*)d_in[9];
    const float* bfc  = (const float*)d_in[10];
    float* out = (float*)d_out;

    float *seq0, *h1f;
    __nv_bfloat16 *w0h, *w0l, *w1h, *w1l, *w2h, *w2l;
    cudaGetSymbolAddress((void**)&seq0, g_seq0);
    cudaGetSymbolAddress((void**)&h1f,  g_h1f);
    cudaGetSymbolAddress((void**)&w0h, g_W0hi); cudaGetSymbolAddress((void**)&w0l, g_W0lo);
    cudaGetSymbolAddress((void**)&w1h, g_W1hi); cudaGetSymbolAddress((void**)&w1l, g_W1lo);
    cudaGetSymbolAddress((void**)&w2h, g_W2hi); cudaGetSymbolAddress((void**)&w2l, g_W2lo);

    cudaFuncSetAttribute(rnn_mma_persistent,
                         cudaFuncAttributeMaxDynamicSharedMemorySize, SM_TOTAL);

    xp0_kernel<<<(BATCH * SEQ) / 16, 256>>>(x, Wih0, bih0, bhh0, seq0);
    wconv_kernel<<<(HID * HID) / 256, 256>>>(Whh0, w0h, w0l);
    wconv_kernel<<<(HID * HID) / 256, 256>>>(Wih1, w1h, w1l);
    wconv_kernel<<<(HID * HID) / 256, 256>>>(Whh1, w2h, w2l);

    rnn_mma_persistent<<<dim3(16, 8), 128, SM_TOTAL>>>(seq0, bih1, bhh1);

    // L1 final step s = 511 (odd) -> fp32 state in parity-1 buffer
    fc_kernel<<<BATCH, 128>>>(h1f + HSZ, Wfc, bfc, out);

    (void)in_sizes; (void)n_in; (void)out_size;
}

// round 15
// speedup vs baseline: 2.7050x; 1.3830x over previous
#include <cuda_runtime.h>
#include <cuda_bf16.h>
#include <math.h>
#include <cstdint>

#define BATCH 256
#define SEQ   512
#define INPUT 64
#define HID   512
#define HSZ   (BATCH * HID)

// ---------------- scratch (device globals; no allocations) ------------------
__device__ float g_seq0[(size_t)BATCH * SEQ * HID];            // xp0 (b, t, h)
__device__ __nv_bfloat16 g_hxhi[2 * HSZ], g_hxlo[2 * HSZ];     // L0 state / handoff
__device__ __nv_bfloat16 g_h1hi[2 * HSZ], g_h1lo[2 * HSZ];     // L1 state
__device__ float g_h1f[2 * HSZ];                               // L1 state fp32 (FC)
__device__ __nv_bfloat16 g_W0hi[HID * HID], g_W0lo[HID * HID]; // Whh0
__device__ __nv_bfloat16 g_W1hi[HID * HID], g_W1lo[HID * HID]; // Wih1
__device__ __nv_bfloat16 g_W2hi[HID * HID], g_W2lo[HID * HID]; // Whh1
__device__ unsigned          g_bar_count;
__device__ volatile unsigned g_bar_gen;

// ---------------------------------------------------------------------------
__device__ __forceinline__ void grid_barrier(unsigned nblocks) {
    __syncthreads();
    if (threadIdx.x == 0) {
        unsigned gen = g_bar_gen;
        __threadfence();
        unsigned arrived = atomicAdd(&g_bar_count, 1u);
        if (arrived == nblocks - 1u) {
            *(volatile unsigned*)&g_bar_count = 0u;
            __threadfence();
            g_bar_gen = gen + 1u;
        } else {
            while (g_bar_gen == gen) { }
            __threadfence();
        }
    }
    __syncthreads();
}

__device__ __forceinline__ uint32_t smem_to_u32(const void* p) {
    uint32_t a;
    asm("{ .reg .u64 t; cvta.to.shared.u64 t, %1; cvt.u32.u64 %0, t; }" : "=r"(a) : "l"(p));
    return a;
}

// ---- warp MMA primitives (baseline PTX, compiles for plain sm_103) ---------
__device__ __forceinline__ void ldm_x4(uint32_t* r, uint32_t addr) {
    asm volatile("ldmatrix.sync.aligned.m8n8.x4.shared.b16 {%0,%1,%2,%3}, [%4];"
                 : "=r"(r[0]), "=r"(r[1]), "=r"(r[2]), "=r"(r[3]) : "r"(addr));
}
__device__ __forceinline__ void mma16816(float* d, const uint32_t* a, uint32_t b0, uint32_t b1) {
    asm volatile(
        "mma.sync.aligned.m16n8k16.row.col.f32.bf16.bf16.f32 "
        "{%0,%1,%2,%3}, {%4,%5,%6,%7}, {%8,%9}, {%0,%1,%2,%3};"
        : "+f"(d[0]), "+f"(d[1]), "+f"(d[2]), "+f"(d[3])
        : "r"(a[0]), "r"(a[1]), "r"(a[2]), "r"(a[3]), "r"(b0), "r"(b1));
}

// ---------------------------------------------------------------------------
// xp0 (proven)
__global__ __launch_bounds__(256) void xp0_kernel(
    const float* __restrict__ x, const float* __restrict__ Wih,
    const float* __restrict__ bih, const float* __restrict__ bhh,
    float* __restrict__ out)
{
    __shared__ float xs[16][INPUT];
    const int bt0 = blockIdx.x * 16;
    const int tid = threadIdx.x;
    {
        int r = tid >> 4, c4 = (tid & 15) * 4;
        float4 v = *reinterpret_cast<const float4*>(&x[(size_t)(bt0 + r) * INPUT + c4]);
        xs[r][c4 + 0] = v.x; xs[r][c4 + 1] = v.y; xs[r][c4 + 2] = v.z; xs[r][c4 + 3] = v.w;
    }
    __syncthreads();
    #pragma unroll
    for (int hh = 0; hh < 2; hh++) {
        const int h = tid + hh * 256;
        const float bias = bih[h] + bhh[h];
        float acc[16];
        #pragma unroll
        for (int r = 0; r < 16; r++) acc[r] = 0.0f;
        const float4* wrow = reinterpret_cast<const float4*>(&Wih[(size_t)h * INPUT]);
        #pragma unroll
        for (int k4 = 0; k4 < INPUT / 4; k4++) {
            float4 w = wrow[k4];
            #pragma unroll
            for (int r = 0; r < 16; r++) {
                float4 xv = *reinterpret_cast<const float4*>(&xs[r][k4 * 4]);
                acc[r] = fmaf(w.x, xv.x, acc[r]); acc[r] = fmaf(w.y, xv.y, acc[r]);
                acc[r] = fmaf(w.z, xv.z, acc[r]); acc[r] = fmaf(w.w, xv.w, acc[r]);
            }
        }
        #pragma unroll
        for (int r = 0; r < 16; r++)
            out[(size_t)(bt0 + r) * HID + h] = acc[r] + bias;
    }
}

// W fp32 -> (hi, lo) bf16
__global__ __launch_bounds__(256) void wconv_kernel(
    const float* __restrict__ W, __nv_bfloat16* __restrict__ hi,
    __nv_bfloat16* __restrict__ lo)
{
    int i = blockIdx.x * 256 + threadIdx.x;
    float w = W[i];
    __nv_bfloat16 h = __float2bfloat16(w);
    hi[i] = h;
    lo[i] = __float2bfloat16(w - __bfloat162float(h));
}

// ---------------------------------------------------------------------------
// smem layout (bytes). A/W chunks are [32 rows][128B], granule swizzle g^(r&7).
#define SM_BIAS  0                       // 128 B
#define SM_RED   128                     // 4096 B split-K reduction
#define SM_W     4224
#define W_BLOCK  4096
#define SM_A     (SM_W + 6 * 8 * W_BLOCK)      // 200832
#define SM_TOTAL (SM_A + 2 * 2 * 4096)         // 217216

// A-chunk staging (256 threads): thread -> row tid>>3, granule tid&7 (hi + lo)
struct SR { uint4 hi, lo; };

__device__ __forceinline__ void sr_load(SR& s, const __nv_bfloat16* __restrict__ hi,
                                        const __nv_bfloat16* __restrict__ lo,
                                        int b0, int kc) {
    const int r = threadIdx.x >> 3, g = threadIdx.x & 7;
    s.hi = __ldcg(reinterpret_cast<const uint4*>(hi + (size_t)(b0 + r) * HID + kc) + g);
    s.lo = __ldcg(reinterpret_cast<const uint4*>(lo + (size_t)(b0 + r) * HID + kc) + g);
}
__device__ __forceinline__ void sr_store(const SR& s, char* abuf) {
    const int r = threadIdx.x >> 3, g = threadIdx.x & 7;
    const int gs = (g ^ (r & 7)) * 16;
    *reinterpret_cast<uint4*>(abuf + r * 128 + gs) = s.hi;
    *reinterpret_cast<uint4*>(abuf + 4096 + r * 128 + gs) = s.lo;
}

// per-lane fragment addressing
struct LaneAddr { int aOff, aXor, aKh, wOff, wXor, wKh, jbase; };

// One 64-k chunk, this warp's K-half only: 8 ldmatrix.x4 + 12 HMMA.
__device__ __forceinline__ void compute_chunk(
    uint32_t aHiB, uint32_t wHiB, const LaneAddr& L, float* accA, float* accB)
{
    #pragma unroll
    for (int j = 0; j < 2; j++) {
        const int jj = L.jbase + j;
        uint32_t ahi[4], alo[4], whi[4], wlo[4];
        const uint32_t ga = (uint32_t)(((2 * jj + L.aKh) ^ L.aXor) * 16);
        const uint32_t gw = (uint32_t)(((2 * jj + L.wKh) ^ L.wXor) * 16);
        ldm_x4(ahi, aHiB + L.aOff + ga);
        ldm_x4(alo, aHiB + 4096 + L.aOff + ga);
        ldm_x4(whi, wHiB + L.wOff + gw);
        ldm_x4(wlo, wHiB + 8 * W_BLOCK + L.wOff + gw);
        mma16816(accA, ahi, whi[0], whi[1]);
        mma16816(accA, alo, whi[0], whi[1]);
        mma16816(accA, ahi, wlo[0], wlo[1]);
        mma16816(accB, ahi, whi[2], whi[3]);
        mma16816(accB, alo, whi[2], whi[3]);
        mma16816(accB, ahi, wlo[2], wlo[3]);
    }
}

// ---------------------------------------------------------------------------
// Persistent HMMA wavefront kernel. grid (16, 8) = 128 CTAs x 256 threads.
// 8 warps: km = warp&1 (K half), wq = warp>>1 -> wm = wq&1 (b half),
// wn = wq>>1 (h half). Split-K partials reduced via smem.
__global__ __launch_bounds__(256) void rnn_mma_persistent(
    const float* __restrict__ xp,
    const float* __restrict__ bih1, const float* __restrict__ bhh1)
{
    extern __shared__ char smem[];
    const uint32_t smem_base = smem_to_u32(smem);
    const int tid = threadIdx.x;
    const int h0  = blockIdx.x * 32;
    const int b0  = blockIdx.y * 32;
    const unsigned nblocks = gridDim.x * gridDim.y;

    if (tid < 32)
        *reinterpret_cast<float*>(smem + SM_BIAS + tid * 4) = bih1[h0 + tid] + bhh1[h0 + tid];

    // ---- build resident W tiles: block index = mh*8 + c, mh = matrix*2 + hilo
    // (W0hi 0-7, W0lo 8-15, W1hi 16-23, W1lo 24-31, W2hi 32-39, W2lo 40-47)
    {
        const int r = tid >> 3, g = tid & 7;
        const int gs = (g ^ (r & 7)) * 16;
        #pragma unroll 1
        for (int mh = 0; mh < 6; mh++) {
            const __nv_bfloat16* src =
                (mh == 0) ? g_W0hi : (mh == 1) ? g_W0lo :
                (mh == 2) ? g_W1hi : (mh == 3) ? g_W1lo :
                (mh == 4) ? g_W2hi : g_W2lo;
            #pragma unroll 1
            for (int c = 0; c < 8; c++) {
                uint4 v = __ldg(reinterpret_cast<const uint4*>(
                    src + (size_t)(h0 + r) * HID + c * 64) + g);
                *reinterpret_cast<uint4*>(
                    smem + SM_W + (size_t)(mh * 8 + c) * W_BLOCK + r * 128 + gs) = v;
            }
        }
    }

    // ---- zero initial parity-1 states ----
    if (tid < 128) {
        const int r = tid >> 2, cb = (tid & 3) * 8;
        const size_t o = (size_t)HSZ + (size_t)(b0 + r) * HID + h0 + cb;
        const uint4 z = make_uint4(0, 0, 0, 0);
        __stcg(reinterpret_cast<uint4*>(g_hxhi + o), z);
        __stcg(reinterpret_cast<uint4*>(g_hxlo + o), z);
        __stcg(reinterpret_cast<uint4*>(g_h1hi + o), z);
        __stcg(reinterpret_cast<uint4*>(g_h1lo + o), z);
    }
    __syncthreads();
    grid_barrier(nblocks);

    // lane/warp constants
    const int warp = tid >> 5, lane = tid & 31;
    const int km = warp & 1;          // K half
    const int wq = warp >> 1;         // output quadrant
    const int wm = wq & 1, wn = wq >> 1;
    LaneAddr L;
    {
        const int blk = lane >> 3, lr = lane & 7;
        const int aRow = wm * 16 + (blk & 1) * 8 + lr;
        const int wRow = wn * 16 + (blk >> 1) * 8 + lr;
        L.aOff = aRow * 128; L.aXor = aRow & 7; L.aKh = blk >> 1;
        L.wOff = wRow * 128; L.wXor = wRow & 7; L.wKh = blk & 1;
        L.jbase = km * 2;
    }
    const int erow = b0 + wm * 16 + (lane >> 2);
    const int ecol = h0 + wn * 16 + (lane & 3) * 2;
    float* red = reinterpret_cast<float*>(smem + SM_RED) + (wq * 32 + lane) * 8;

    const uint32_t aB0 = smem_base + SM_A;
    const uint32_t aB1 = smem_base + SM_A + 8192;

    for (int t = 0; t <= SEQ; t++) {
        const size_t l0in  = (size_t)((t + 1) & 1) * HSZ;
        const size_t l0out = (size_t)(t & 1) * HSZ;
        const int s = t - 1;
        const size_t xOff  = (size_t)(s & 1) * HSZ;
        const size_t l1in  = (size_t)((s + 1) & 1) * HSZ;
        const size_t l1out = (size_t)(s & 1) * HSZ;

        SR sr, sr1;
        if (t < SEQ) sr_load(sr, g_hxhi + l0in, g_hxlo + l0in, b0, 0);
        if (t > 0)   sr_load(sr1, g_hxhi + xOff, g_hxlo + xOff, b0, 0);

        // ================= layer 0, step t =================
        if (t < SEQ) {
            float acc0[4] = {0, 0, 0, 0}, acc1[4] = {0, 0, 0, 0};
            #pragma unroll 1
            for (int c = 0; c < 8; c++) {
                char* abuf = smem + SM_A + (size_t)(c & 1) * 8192;
                sr_store(sr, abuf);
                __syncthreads();
                if (c + 1 < 8)
                    sr_load(sr, g_hxhi + l0in, g_hxlo + l0in, b0, (c + 1) * 64);
                compute_chunk((c & 1) ? aB1 : aB0,
                              smem_base + SM_W + (uint32_t)c * W_BLOCK,   // W0hi blocks 0-7
                              L, acc0, acc1);
            }
            // split-K reduce
            if (km == 1) {
                #pragma unroll
                for (int i = 0; i < 4; i++) { red[i] = acc0[i]; red[4 + i] = acc1[i]; }
            }
            __syncthreads();
            if (km == 0) {
                #pragma unroll
                for (int i = 0; i < 4; i++) { acc0[i] += red[i]; acc1[i] += red[4 + i]; }
                // epilogue: + xp, tanh, hi/lo split, store
                #pragma unroll
                for (int tile = 0; tile < 2; tile++) {
                    const int h = ecol + tile * 8;
                    const float* ac = tile ? acc1 : acc0;
                    #pragma unroll
                    for (int half = 0; half < 2; half++) {
                        const int b = erow + half * 8;
                        const float2 xv = *reinterpret_cast<const float2*>(
                            &xp[((size_t)b * SEQ + t) * HID + h]);
                        float v0 = tanhf(ac[half * 2 + 0] + xv.x);
                        float v1 = tanhf(ac[half * 2 + 1] + xv.y);
                        __nv_bfloat162 hh = __float22bfloat162_rn(make_float2(v0, v1));
                        float r0 = v0 - __bfloat162float(hh.x);
                        float r1 = v1 - __bfloat162float(hh.y);
                        __nv_bfloat162 ll = __float22bfloat162_rn(make_float2(r0, r1));
                        const size_t o = l0out + (size_t)b * HID + h;
                        __stcg(reinterpret_cast<uint32_t*>(g_hxhi + o),
                               *reinterpret_cast<uint32_t*>(&hh));
                        __stcg(reinterpret_cast<uint32_t*>(g_hxlo + o),
                               *reinterpret_cast<uint32_t*>(&ll));
                    }
                }
            }
        }

        // ================= layer 1, step s = t-1 =================
        if (t > 0) {
            float acc0[4] = {0, 0, 0, 0}, acc1[4] = {0, 0, 0, 0};
            #pragma unroll 1
            for (int c = 0; c < 16; c++) {
                char* abuf = smem + SM_A + (size_t)(c & 1) * 8192;
                sr_store(sr1, abuf);
                __syncthreads();
                if (c + 1 < 16) {
                    const int nx = c + 1;
                    if (nx < 8)
                        sr_load(sr1, g_hxhi + xOff, g_hxlo + xOff, b0, nx * 64);
                    else
                        sr_load(sr1, g_h1hi + l1in, g_h1lo + l1in, b0, (nx - 8) * 64);
                }
                const int m = (c < 8) ? 1 : 2;
                // FIX (R14 bug): W tile base is m*16 blocks (hi run), lo at +8 blocks.
                compute_chunk((c & 1) ? aB1 : aB0,
                              smem_base + SM_W + (uint32_t)(m * 16 + (c & 7)) * W_BLOCK,
                              L, acc0, acc1);
            }
            if (km == 1) {
                #pragma unroll
                for (int i = 0; i < 4; i++) { red[i] = acc0[i]; red[4 + i] = acc1[i]; }
            }
            __syncthreads();
            if (km == 0) {
                #pragma unroll
                for (int i = 0; i < 4; i++) { acc0[i] += red[i]; acc1[i] += red[4 + i]; }
                #pragma unroll
                for (int tile = 0; tile < 2; tile++) {
                    const int h = ecol + tile * 8;
                    const float* ac = tile ? acc1 : acc0;
                    const float2 ev = *reinterpret_cast<const float2*>(
                        smem + SM_BIAS + (h - h0) * 4);
                    #pragma unroll
                    for (int half = 0; half < 2; half++) {
                        const int b = erow + half * 8;
                        float v0 = tanhf(ac[half * 2 + 0] + ev.x);
                        float v1 = tanhf(ac[half * 2 + 1] + ev.y);
                        __nv_bfloat162 hh = __float22bfloat162_rn(make_float2(v0, v1));
                        float r0 = v0 - __bfloat162float(hh.x);
                        float r1 = v1 - __bfloat162float(hh.y);
                        __nv_bfloat162 ll = __float22bfloat162_rn(make_float2(r0, r1));
                        const size_t o = l1out + (size_t)b * HID + h;
                        __stcg(reinterpret_cast<uint32_t*>(g_h1hi + o),
                               *reinterpret_cast<uint32_t*>(&hh));
                        __stcg(reinterpret_cast<uint32_t*>(g_h1lo + o),
                               *reinterpret_cast<uint32_t*>(&ll));
                        __stcg(reinterpret_cast<float2*>(g_h1f + o), make_float2(v0, v1));
                    }
                }
            }
        }

        grid_barrier(nblocks);
    }
}

// ---------------------------------------------------------------------------
__global__ __launch_bounds__(128) void fc_kernel(
    const float* __restrict__ h, const float* __restrict__ Wfc,
    const float* __restrict__ bfc, float* __restrict__ out)
{
    const int bq = blockIdx.x;
    const int tid = threadIdx.x;
    float s = 0.f;
    for (int k = tid; k < HID; k += 128)
        s = fmaf(h[(size_t)bq * HID + k], Wfc[k], s);
    #pragma unroll
    for (int o = 16; o > 0; o >>= 1) s += __shfl_xor_sync(0xffffffffu, s, o);
    __shared__ float red[4];
    if ((tid & 31) == 0) red[tid >> 5] = s;
    __syncthreads();
    if (tid == 0) out[bq] = red[0] + red[1] + red[2] + red[3] + bfc[0];
}

// ---------------------------------------------------------------------------
extern "C" void kernel_launch(void* const* d_in, const int* in_sizes, int n_in,
                              void* d_out, int out_size)
{
    const float* x    = (const float*)d_in[0];
    const float* Wih0 = (const float*)d_in[1];
    const float* Whh0 = (const float*)d_in[2];
    const float* bih0 = (const float*)d_in[3];
    const float* bhh0 = (const float*)d_in[4];
    const float* Wih1 = (const float*)d_in[5];
    const float* Whh1 = (const float*)d_in[6];
    const float* bih1 = (const float*)d_in[7];
    const float* bhh1 = (const float*)d_in[8];
    const float* Wfc  = (const float*)d_in[9];
    const float* bfc  = (const float*)d_in[10];
    float* out = (float*)d_out;

    float *seq0, *h1f;
    __nv_bfloat16 *w0h, *w0l, *w1h, *w1l, *w2h, *w2l;
    cudaGetSymbolAddress((void**)&seq0, g_seq0);
    cudaGetSymbolAddress((void**)&h1f,  g_h1f);
    cudaGetSymbolAddress((void**)&w0h, g_W0hi); cudaGetSymbolAddress((void**)&w0l, g_W0lo);
    cudaGetSymbolAddress((void**)&w1h, g_W1hi); cudaGetSymbolAddress((void**)&w1l, g_W1lo);
    cudaGetSymbolAddress((void**)&w2h, g_W2hi); cudaGetSymbolAddress((void**)&w2l, g_W2lo);

    cudaFuncSetAttribute(rnn_mma_persistent,
                         cudaFuncAttributeMaxDynamicSharedMemorySize, SM_TOTAL);

    xp0_kernel<<<(BATCH * SEQ) / 16, 256>>>(x, Wih0, bih0, bhh0, seq0);
    wconv_kernel<<<(HID * HID) / 256, 256>>>(Whh0, w0h, w0l);
    wconv_kernel<<<(HID * HID) / 256, 256>>>(Wih1, w1h, w1l);
    wconv_kernel<<<(HID * HID) / 256, 256>>>(Whh1, w2h, w2l);

    rnn_mma_persistent<<<dim3(16, 8), 256, SM_TOTAL>>>(seq0, bih1, bhh1);

    // L1 final step s = 511 (odd) -> fp32 state in parity-1 buffer
    fc_kernel<<<BATCH, 128>>>(h1f + HSZ, Wfc, bfc, out);

    (void)in_sizes; (void)n_in; (void)out_size;
}

// round 16
// speedup vs baseline: 3.5830x; 1.3246x over previous
#include <cuda_runtime.h>
#include <cuda_bf16.h>
#include <math.h>
#include <cstdint>

#define BATCH 256
#define SEQ   512
#define INPUT 64
#define HID   512
#define HSZ   (BATCH * HID)

// ---------------- scratch (device globals; no allocations) ------------------
__device__ float g_seq0[(size_t)BATCH * SEQ * HID];            // xp0 (b, t, h)
__device__ __nv_bfloat16 g_hxhi[2 * HSZ], g_hxlo[2 * HSZ];     // L0 state / handoff
__device__ __nv_bfloat16 g_h1hi[2 * HSZ], g_h1lo[2 * HSZ];     // L1 state
__device__ float g_h1f[2 * HSZ];                               // L1 state fp32 (FC)
__device__ __nv_bfloat16 g_W0hi[HID * HID], g_W0lo[HID * HID]; // Whh0
__device__ __nv_bfloat16 g_W1hi[HID * HID], g_W1lo[HID * HID]; // Wih1
__device__ __nv_bfloat16 g_W2hi[HID * HID], g_W2lo[HID * HID]; // Whh1
__device__ unsigned          g_bar_count;
__device__ volatile unsigned g_bar_gen;

// ---------------------------------------------------------------------------
__device__ __forceinline__ void grid_barrier(unsigned nblocks) {
    __syncthreads();
    if (threadIdx.x == 0) {
        unsigned gen = g_bar_gen;
        __threadfence();
        unsigned arrived = atomicAdd(&g_bar_count, 1u);
        if (arrived == nblocks - 1u) {
            *(volatile unsigned*)&g_bar_count = 0u;
            __threadfence();
            g_bar_gen = gen + 1u;
        } else {
            while (g_bar_gen == gen) { }
            __threadfence();
        }
    }
    __syncthreads();
}

__device__ __forceinline__ uint32_t smem_to_u32(const void* p) {
    uint32_t a;
    asm("{ .reg .u64 t; cvta.to.shared.u64 t, %1; cvt.u32.u64 %0, t; }" : "=r"(a) : "l"(p));
    return a;
}

// ---- warp MMA primitives (baseline PTX, compiles for plain sm_103) ---------
__device__ __forceinline__ void ldm_x4(uint32_t* r, uint32_t addr) {
    asm volatile("ldmatrix.sync.aligned.m8n8.x4.shared.b16 {%0,%1,%2,%3}, [%4];"
                 : "=r"(r[0]), "=r"(r[1]), "=r"(r[2]), "=r"(r[3]) : "r"(addr));
}
__device__ __forceinline__ void mma16816(float* d, const uint32_t* a, uint32_t b0, uint32_t b1) {
    asm volatile(
        "mma.sync.aligned.m16n8k16.row.col.f32.bf16.bf16.f32 "
        "{%0,%1,%2,%3}, {%4,%5,%6,%7}, {%8,%9}, {%0,%1,%2,%3};"
        : "+f"(d[0]), "+f"(d[1]), "+f"(d[2]), "+f"(d[3])
        : "r"(a[0]), "r"(a[1]), "r"(a[2]), "r"(a[3]), "r"(b0), "r"(b1));
}

// ---------------------------------------------------------------------------
// xp0 (proven)
__global__ __launch_bounds__(256) void xp0_kernel(
    const float* __restrict__ x, const float* __restrict__ Wih,
    const float* __restrict__ bih, const float* __restrict__ bhh,
    float* __restrict__ out)
{
    __shared__ float xs[16][INPUT];
    const int bt0 = blockIdx.x * 16;
    const int tid = threadIdx.x;
    {
        int r = tid >> 4, c4 = (tid & 15) * 4;
        float4 v = *reinterpret_cast<const float4*>(&x[(size_t)(bt0 + r) * INPUT + c4]);
        xs[r][c4 + 0] = v.x; xs[r][c4 + 1] = v.y; xs[r][c4 + 2] = v.z; xs[r][c4 + 3] = v.w;
    }
    __syncthreads();
    #pragma unroll
    for (int hh = 0; hh < 2; hh++) {
        const int h = tid + hh * 256;
        const float bias = bih[h] + bhh[h];
        float acc[16];
        #pragma unroll
        for (int r = 0; r < 16; r++) acc[r] = 0.0f;
        const float4* wrow = reinterpret_cast<const float4*>(&Wih[(size_t)h * INPUT]);
        #pragma unroll
        for (int k4 = 0; k4 < INPUT / 4; k4++) {
            float4 w = wrow[k4];
            #pragma unroll
            for (int r = 0; r < 16; r++) {
                float4 xv = *reinterpret_cast<const float4*>(&xs[r][k4 * 4]);
                acc[r] = fmaf(w.x, xv.x, acc[r]); acc[r] = fmaf(w.y, xv.y, acc[r]);
                acc[r] = fmaf(w.z, xv.z, acc[r]); acc[r] = fmaf(w.w, xv.w, acc[r]);
            }
        }
        #pragma unroll
        for (int r = 0; r < 16; r++)
            out[(size_t)(bt0 + r) * HID + h] = acc[r] + bias;
    }
}

// W fp32 -> (hi, lo) bf16
__global__ __launch_bounds__(256) void wconv_kernel(
    const float* __restrict__ W, __nv_bfloat16* __restrict__ hi,
    __nv_bfloat16* __restrict__ lo)
{
    int i = blockIdx.x * 256 + threadIdx.x;
    float w = W[i];
    __nv_bfloat16 h = __float2bfloat16(w);
    hi[i] = h;
    lo[i] = __float2bfloat16(w - __bfloat162float(h));
}

// ---------------------------------------------------------------------------
// smem layout (bytes). A/W chunks are [32 rows][128B], granule swizzle g^(r&7).
// Reduction region ALIASES staging buffer 3 (dead at reduce time; hazards
// guarded by the extra pre-reduce sync + the next group's sync).
#define SM_BIAS  0                             // 128 B
#define SM_W     128
#define W_BLOCK  4096
#define SM_A     (SM_W + 48 * W_BLOCK)         // 196736; 4 buffers x 8192
#define SM_RED   (SM_A + 3 * 8192)             // aliases buf3
#define SM_TOTAL (SM_A + 4 * 8192)             // 229504 <= 232448

// A-chunk staging (256 threads): thread -> row tid>>3, granule tid&7 (hi + lo)
struct SR { uint4 hi, lo; };

__device__ __forceinline__ void sr_load(SR& s, const __nv_bfloat16* __restrict__ hi,
                                        const __nv_bfloat16* __restrict__ lo,
                                        int b0, int kc) {
    const int r = threadIdx.x >> 3, g = threadIdx.x & 7;
    s.hi = __ldcg(reinterpret_cast<const uint4*>(hi + (size_t)(b0 + r) * HID + kc) + g);
    s.lo = __ldcg(reinterpret_cast<const uint4*>(lo + (size_t)(b0 + r) * HID + kc) + g);
}
__device__ __forceinline__ void sr_store(const SR& s, char* abuf) {
    const int r = threadIdx.x >> 3, g = threadIdx.x & 7;
    const int gs = (g ^ (r & 7)) * 16;
    *reinterpret_cast<uint4*>(abuf + r * 128 + gs) = s.hi;
    *reinterpret_cast<uint4*>(abuf + 4096 + r * 128 + gs) = s.lo;
}

// per-lane fragment addressing
struct LaneAddr { int aOff, aXor, aKh, wOff, wXor, wKh, jbase; };

// One 64-k chunk, this warp's K-half: 8 ldmatrix.x4 + 12 HMMA into SIX
// independent accumulator quads (3 split terms x 2 h-tiles) — no acc chains.
__device__ __forceinline__ void compute_chunk(
    uint32_t aHiB, uint32_t wHiB, const LaneAddr& L, float* a0, float* a1)
{
    #pragma unroll
    for (int j = 0; j < 2; j++) {
        const int jj = L.jbase + j;
        uint32_t ahi[4], alo[4], whi[4], wlo[4];
        const uint32_t ga = (uint32_t)(((2 * jj + L.aKh) ^ L.aXor) * 16);
        const uint32_t gw = (uint32_t)(((2 * jj + L.wKh) ^ L.wXor) * 16);
        ldm_x4(ahi, aHiB + L.aOff + ga);
        ldm_x4(alo, aHiB + 4096 + L.aOff + ga);
        ldm_x4(whi, wHiB + L.wOff + gw);
        ldm_x4(wlo, wHiB + 8 * W_BLOCK + L.wOff + gw);
        mma16816(a0 + 0, ahi, whi[0], whi[1]);   // hi*Whi
        mma16816(a0 + 4, alo, whi[0], whi[1]);   // lo*Whi
        mma16816(a0 + 8, ahi, wlo[0], wlo[1]);   // hi*Wlo
        mma16816(a1 + 0, ahi, whi[2], whi[3]);
        mma16816(a1 + 4, alo, whi[2], whi[3]);
        mma16816(a1 + 8, ahi, wlo[2], wlo[3]);
    }
}

// ---------------------------------------------------------------------------
// Persistent HMMA wavefront kernel. grid (16, 8) = 128 CTAs x 256 threads.
// 8 warps: km = warp&1 (K half), wq = warp>>1 -> wm = wq&1 (b half),
// wn = wq>>1 (h half). Two 64-k chunks per sync (4 staging buffers).
__global__ __launch_bounds__(256) void rnn_mma_persistent(
    const float* __restrict__ xp,
    const float* __restrict__ bih1, const float* __restrict__ bhh1)
{
    extern __shared__ char smem[];
    const uint32_t smem_base = smem_to_u32(smem);
    const int tid = threadIdx.x;
    const int h0  = blockIdx.x * 32;
    const int b0  = blockIdx.y * 32;
    const unsigned nblocks = gridDim.x * gridDim.y;

    if (tid < 32)
        *reinterpret_cast<float*>(smem + SM_BIAS + tid * 4) = bih1[h0 + tid] + bhh1[h0 + tid];

    // ---- build resident W tiles: block index = mh*8 + c, mh = matrix*2 + hilo
    {
        const int r = tid >> 3, g = tid & 7;
        const int gs = (g ^ (r & 7)) * 16;
        #pragma unroll 1
        for (int mh = 0; mh < 6; mh++) {
            const __nv_bfloat16* src =
                (mh == 0) ? g_W0hi : (mh == 1) ? g_W0lo :
                (mh == 2) ? g_W1hi : (mh == 3) ? g_W1lo :
                (mh == 4) ? g_W2hi : g_W2lo;
            #pragma unroll 1
            for (int c = 0; c < 8; c++) {
                uint4 v = __ldg(reinterpret_cast<const uint4*>(
                    src + (size_t)(h0 + r) * HID + c * 64) + g);
                *reinterpret_cast<uint4*>(
                    smem + SM_W + (size_t)(mh * 8 + c) * W_BLOCK + r * 128 + gs) = v;
            }
        }
    }

    // ---- zero initial parity-1 states ----
    if (tid < 128) {
        const int r = tid >> 2, cb = (tid & 3) * 8;
        const size_t o = (size_t)HSZ + (size_t)(b0 + r) * HID + h0 + cb;
        const uint4 z = make_uint4(0, 0, 0, 0);
        __stcg(reinterpret_cast<uint4*>(g_hxhi + o), z);
        __stcg(reinterpret_cast<uint4*>(g_hxlo + o), z);
        __stcg(reinterpret_cast<uint4*>(g_h1hi + o), z);
        __stcg(reinterpret_cast<uint4*>(g_h1lo + o), z);
    }
    __syncthreads();
    grid_barrier(nblocks);

    // lane/warp constants
    const int warp = tid >> 5, lane = tid & 31;
    const int km = warp & 1;          // K half
    const int wq = warp >> 1;         // output quadrant
    const int wm = wq & 1, wn = wq >> 1;
    LaneAddr L;
    {
        const int blk = lane >> 3, lr = lane & 7;
        const int aRow = wm * 16 + (blk & 1) * 8 + lr;
        const int wRow = wn * 16 + (blk >> 1) * 8 + lr;
        L.aOff = aRow * 128; L.aXor = aRow & 7; L.aKh = blk >> 1;
        L.wOff = wRow * 128; L.wXor = wRow & 7; L.wKh = blk & 1;
        L.jbase = km * 2;
    }
    const int erow = b0 + wm * 16 + (lane >> 2);
    const int ecol = h0 + wn * 16 + (lane & 3) * 2;
    float* red = reinterpret_cast<float*>(smem + SM_RED) + (wq * 32 + lane) * 8;

    for (int t = 0; t <= SEQ; t++) {
        const size_t l0in  = (size_t)((t + 1) & 1) * HSZ;
        const size_t l0out = (size_t)(t & 1) * HSZ;
        const int s = t - 1;
        const size_t xOff  = (size_t)(s & 1) * HSZ;        // == l0in parity
        const size_t l1in  = (size_t)((s + 1) & 1) * HSZ;
        const size_t l1out = (size_t)(s & 1) * HSZ;

        // prefetch: L0 group 0, L1 group 0, and L0's xp epilogue values
        SR sa, sb, sa1, sb1;
        float2 xv[2][2];
        if (t < SEQ) {
            sr_load(sa, g_hxhi + l0in, g_hxlo + l0in, b0, 0);
            sr_load(sb, g_hxhi + l0in, g_hxlo + l0in, b0, 64);
            if (km == 0) {
                #pragma unroll
                for (int tile = 0; tile < 2; tile++)
                    #pragma unroll
                    for (int half = 0; half < 2; half++)
                        xv[tile][half] = __ldg(reinterpret_cast<const float2*>(
                            &xp[((size_t)(erow + half * 8) * SEQ + t) * HID
                                + ecol + tile * 8]));
            }
        }
        if (t > 0) {
            sr_load(sa1, g_hxhi + xOff, g_hxlo + xOff, b0, 0);
            sr_load(sb1, g_hxhi + xOff, g_hxlo + xOff, b0, 64);
        }

        // ================= layer 0, step t =================
        if (t < SEQ) {
            float acc0[12], acc1[12];
            #pragma unroll
            for (int i = 0; i < 12; i++) { acc0[i] = 0.f; acc1[i] = 0.f; }
            #pragma unroll 1
            for (int g = 0; g < 4; g++) {               // 2 chunks per group
                char* bA = smem + SM_A + (size_t)(g & 1) * 16384;
                char* bB = bA + 8192;
                sr_store(sa, bA);
                sr_store(sb, bB);
                __syncthreads();
                if (g + 1 < 4) {
                    sr_load(sa, g_hxhi + l0in, g_hxlo + l0in, b0, (2 * g + 2) * 64);
                    sr_load(sb, g_hxhi + l0in, g_hxlo + l0in, b0, (2 * g + 3) * 64);
                }
                compute_chunk(smem_base + SM_A + (uint32_t)(g & 1) * 16384,
                              smem_base + SM_W + (uint32_t)(2 * g) * W_BLOCK,
                              L, acc0, acc1);
                compute_chunk(smem_base + SM_A + (uint32_t)(g & 1) * 16384 + 8192,
                              smem_base + SM_W + (uint32_t)(2 * g + 1) * W_BLOCK,
                              L, acc0, acc1);
            }
            __syncthreads();                             // all reads of buf3 done
            if (km == 1) {
                #pragma unroll
                for (int i = 0; i < 4; i++) {
                    red[i]     = acc0[i] + acc0[4 + i] + acc0[8 + i];
                    red[4 + i] = acc1[i] + acc1[4 + i] + acc1[8 + i];
                }
            }
            __syncthreads();
            if (km == 0) {
                #pragma unroll
                for (int tile = 0; tile < 2; tile++) {
                    const float* ac = tile ? acc1 : acc0;
                    const float* rd = red + tile * 4;
                    const int h = ecol + tile * 8;
                    #pragma unroll
                    for (int half = 0; half < 2; half++) {
                        const int b = erow + half * 8;
                        float c0 = ac[half * 2 + 0] + ac[4 + half * 2 + 0]
                                 + ac[8 + half * 2 + 0] + rd[half * 2 + 0];
                        float c1 = ac[half * 2 + 1] + ac[4 + half * 2 + 1]
                                 + ac[8 + half * 2 + 1] + rd[half * 2 + 1];
                        float v0 = tanhf(c0 + xv[tile][half].x);
                        float v1 = tanhf(c1 + xv[tile][half].y);
                        __nv_bfloat162 hh = __float22bfloat162_rn(make_float2(v0, v1));
                        float r0 = v0 - __bfloat162float(hh.x);
                        float r1 = v1 - __bfloat162float(hh.y);
                        __nv_bfloat162 ll = __float22bfloat162_rn(make_float2(r0, r1));
                        const size_t o = l0out + (size_t)b * HID + h;
                        __stcg(reinterpret_cast<uint32_t*>(g_hxhi + o),
                               *reinterpret_cast<uint32_t*>(&hh));
                        __stcg(reinterpret_cast<uint32_t*>(g_hxlo + o),
                               *reinterpret_cast<uint32_t*>(&ll));
                    }
                }
            }
        }

        // ================= layer 1, step s = t-1 =================
        if (t > 0) {
            float acc0[12], acc1[12];
            #pragma unroll
            for (int i = 0; i < 12; i++) { acc0[i] = 0.f; acc1[i] = 0.f; }
            #pragma unroll 1
            for (int g = 0; g < 8; g++) {               // chunks 2g, 2g+1
                char* bA = smem + SM_A + (size_t)(g & 1) * 16384;
                char* bB = bA + 8192;
                sr_store(sa1, bA);
                sr_store(sb1, bB);
                __syncthreads();
                if (g + 1 < 8) {
                    const int c0 = 2 * g + 2, c1 = 2 * g + 3;
                    if (c0 < 8) sr_load(sa1, g_hxhi + xOff, g_hxlo + xOff, b0, c0 * 64);
                    else        sr_load(sa1, g_h1hi + l1in, g_h1lo + l1in, b0, (c0 & 7) * 64);
                    if (c1 < 8) sr_load(sb1, g_hxhi + xOff, g_hxlo + xOff, b0, c1 * 64);
                    else        sr_load(sb1, g_h1hi + l1in, g_h1lo + l1in, b0, (c1 & 7) * 64);
                }
                const int ca = 2 * g, cb2 = 2 * g + 1;
                const int m = (ca < 8) ? 1 : 2;          // W1 blocks 16-23, W2 32-39
                compute_chunk(smem_base + SM_A + (uint32_t)(g & 1) * 16384,
                              smem_base + SM_W + (uint32_t)(m * 16 + (ca & 7)) * W_BLOCK,
                              L, acc0, acc1);
                compute_chunk(smem_base + SM_A + (uint32_t)(g & 1) * 16384 + 8192,
                              smem_base + SM_W + (uint32_t)(m * 16 + (cb2 & 7)) * W_BLOCK,
                              L, acc0, acc1);
            }
            __syncthreads();                             // all reads of buf3 done
            if (km == 1) {
                #pragma unroll
                for (int i = 0; i < 4; i++) {
                    red[i]     = acc0[i] + acc0[4 + i] + acc0[8 + i];
                    red[4 + i] = acc1[i] + acc1[4 + i] + acc1[8 + i];
                }
            }
            __syncthreads();
            if (km == 0) {
                #pragma unroll
                for (int tile = 0; tile < 2; tile++) {
                    const float* ac = tile ? acc1 : acc0;
                    const float* rd = red + tile * 4;
                    const int h = ecol + tile * 8;
                    const float2 ev = *reinterpret_cast<const float2*>(
                        smem + SM_BIAS + (h - h0) * 4);
                    #pragma unroll
                    for (int half = 0; half < 2; half++) {
                        const int b = erow + half * 8;
                        float c0 = ac[half * 2 + 0] + ac[4 + half * 2 + 0]
                                 + ac[8 + half * 2 + 0] + rd[half * 2 + 0];
                        float c1 = ac[half * 2 + 1] + ac[4 + half * 2 + 1]
                                 + ac[8 + half * 2 + 1] + rd[half * 2 + 1];
                        float v0 = tanhf(c0 + ev.x);
                        float v1 = tanhf(c1 + ev.y);
                        __nv_bfloat162 hh = __float22bfloat162_rn(make_float2(v0, v1));
                        float r0 = v0 - __bfloat162float(hh.x);
                        float r1 = v1 - __bfloat162float(hh.y);
                        __nv_bfloat162 ll = __float22bfloat162_rn(make_float2(r0, r1));
                        const size_t o = l1out + (size_t)b * HID + h;
                        __stcg(reinterpret_cast<uint32_t*>(g_h1hi + o),
                               *reinterpret_cast<uint32_t*>(&hh));
                        __stcg(reinterpret_cast<uint32_t*>(g_h1lo + o),
                               *reinterpret_cast<uint32_t*>(&ll));
                        __stcg(reinterpret_cast<float2*>(g_h1f + o), make_float2(v0, v1));
                    }
                }
            }
        }

        grid_barrier(nblocks);
    }
}

// ---------------------------------------------------------------------------
__global__ __launch_bounds__(128) void fc_kernel(
    const float* __restrict__ h, const float* __restrict__ Wfc,
    const float* __restrict__ bfc, float* __restrict__ out)
{
    const int bq = blockIdx.x;
    const int tid = threadIdx.x;
    float s = 0.f;
    for (int k = tid; k < HID; k += 128)
        s = fmaf(h[(size_t)bq * HID + k], Wfc[k], s);
    #pragma unroll
    for (int o = 16; o > 0; o >>= 1) s += __shfl_xor_sync(0xffffffffu, s, o);
    __shared__ float red[4];
    if ((tid & 31) == 0) red[tid >> 5] = s;
    __syncthreads();
    if (tid == 0) out[bq] = red[0] + red[1] + red[2] + red[3] + bfc[0];
}

// ---------------------------------------------------------------------------
extern "C" void kernel_launch(void* const* d_in, const int* in_sizes, int n_in,
                              void* d_out, int out_size)
{
    const float* x    = (const float*)d_in[0];
    const float* Wih0 = (const float*)d_in[1];
    const float* Whh0 = (const float*)d_in[2];
    const float* bih0 = (const float*)d_in[3];
    const float* bhh0 = (const float*)d_in[4];
    const float* Wih1 = (const float*)d_in[5];
    const float* Whh1 = (const float*)d_in[6];
    const float* bih1 = (const float*)d_in[7];
    const float* bhh1 = (const float*)d_in[8];
    const float* Wfc  = (const float*)d_in[9];
    const float* bfc  = (const float*)d_in[10];
    float* out = (float*)d_out;

    float *seq0, *h1f;
    __nv_bfloat16 *w0h, *w0l, *w1h, *w1l, *w2h, *w2l;
    cudaGetSymbolAddress((void**)&seq0, g_seq0);
    cudaGetSymbolAddress((void**)&h1f,  g_h1f);
    cudaGetSymbolAddress((void**)&w0h, g_W0hi); cudaGetSymbolAddress((void**)&w0l, g_W0lo);
    cudaGetSymbolAddress((void**)&w1h, g_W1hi); cudaGetSymbolAddress((void**)&w1l, g_W1lo);
    cudaGetSymbolAddress((void**)&w2h, g_W2hi); cudaGetSymbolAddress((void**)&w2l, g_W2lo);

    cudaFuncSetAttribute(rnn_mma_persistent,
                         cudaFuncAttributeMaxDynamicSharedMemorySize, SM_TOTAL);

    xp0_kernel<<<(BATCH * SEQ) / 16, 256>>>(x, Wih0, bih0, bhh0, seq0);
    wconv_kernel<<<(HID * HID) / 256, 256>>>(Whh0, w0h, w0l);
    wconv_kernel<<<(HID * HID) / 256, 256>>>(Wih1, w1h, w1l);
    wconv_kernel<<<(HID * HID) / 256, 256>>>(Whh1, w2h, w2l);

    rnn_mma_persistent<<<dim3(16, 8), 256, SM_TOTAL>>>(seq0, bih1, bhh1);

    // L1 final step s = 511 (odd) -> fp32 state in parity-1 buffer
    fc_kernel<<<BATCH, 128>>>(h1f + HSZ, Wfc, bfc, out);

    (void)in_sizes; (void)n_in; (void)out_size;
}

// round 17
// speedup vs baseline: 4.3092x; 1.2027x over previous
#include <cuda_runtime.h>
#include <cuda_fp16.h>
#include <math.h>
#include <cstdint>

#define BATCH 256
#define SEQ   512
#define INPUT 64
#define HID   512
#define HSZ   (BATCH * HID)
#define INV2048 4.8828125e-4f

// ---------------- scratch (device globals; no allocations) ------------------
__device__ float g_seq0[(size_t)BATCH * SEQ * HID];      // xp0 (b, t, h)
__device__ __half g_hx[2 * HSZ];                          // L0 state / handoff (fp16)
__device__ __half g_h1[2 * HSZ];                          // L1 state (fp16)
__device__ float g_h1f[2 * HSZ];                          // L1 state fp32 (FC)
__device__ __half g_W0hi[HID * HID], g_W0lo[HID * HID];   // Whh0 (lo scaled by 2^11)
__device__ __half g_W1hi[HID * HID], g_W1lo[HID * HID];   // Wih1
__device__ __half g_W2hi[HID * HID], g_W2lo[HID * HID];   // Whh1
__device__ unsigned          g_bar_count;
__device__ volatile unsigned g_bar_gen;

// ---------------------------------------------------------------------------
__device__ __forceinline__ void grid_barrier(unsigned nblocks) {
    __syncthreads();
    if (threadIdx.x == 0) {
        unsigned gen = g_bar_gen;
        __threadfence();
        unsigned arrived = atomicAdd(&g_bar_count, 1u);
        if (arrived == nblocks - 1u) {
            *(volatile unsigned*)&g_bar_count = 0u;
            __threadfence();
            g_bar_gen = gen + 1u;
        } else {
            while (g_bar_gen == gen) { }
            __threadfence();
        }
    }
    __syncthreads();
}

__device__ __forceinline__ uint32_t smem_to_u32(const void* p) {
    uint32_t a;
    asm("{ .reg .u64 t; cvta.to.shared.u64 t, %1; cvt.u32.u64 %0, t; }" : "=r"(a) : "l"(p));
    return a;
}

// ---- warp MMA primitives (baseline PTX, compiles for plain sm_103) ---------
__device__ __forceinline__ void ldm_x4(uint32_t* r, uint32_t addr) {
    asm volatile("ldmatrix.sync.aligned.m8n8.x4.shared.b16 {%0,%1,%2,%3}, [%4];"
                 : "=r"(r[0]), "=r"(r[1]), "=r"(r[2]), "=r"(r[3]) : "r"(addr));
}
__device__ __forceinline__ void mma16816(float* d, const uint32_t* a, uint32_t b0, uint32_t b1) {
    asm volatile(
        "mma.sync.aligned.m16n8k16.row.col.f32.f16.f16.f32 "
        "{%0,%1,%2,%3}, {%4,%5,%6,%7}, {%8,%9}, {%0,%1,%2,%3};"
        : "+f"(d[0]), "+f"(d[1]), "+f"(d[2]), "+f"(d[3])
        : "r"(a[0]), "r"(a[1]), "r"(a[2]), "r"(a[3]), "r"(b0), "r"(b1));
}

// ---------------------------------------------------------------------------
// xp0 (proven)
__global__ __launch_bounds__(256) void xp0_kernel(
    const float* __restrict__ x, const float* __restrict__ Wih,
    const float* __restrict__ bih, const float* __restrict__ bhh,
    float* __restrict__ out)
{
    __shared__ float xs[16][INPUT];
    const int bt0 = blockIdx.x * 16;
    const int tid = threadIdx.x;
    {
        int r = tid >> 4, c4 = (tid & 15) * 4;
        float4 v = *reinterpret_cast<const float4*>(&x[(size_t)(bt0 + r) * INPUT + c4]);
        xs[r][c4 + 0] = v.x; xs[r][c4 + 1] = v.y; xs[r][c4 + 2] = v.z; xs[r][c4 + 3] = v.w;
    }
    __syncthreads();
    #pragma unroll
    for (int hh = 0; hh < 2; hh++) {
        const int h = tid + hh * 256;
        const float bias = bih[h] + bhh[h];
        float acc[16];
        #pragma unroll
        for (int r = 0; r < 16; r++) acc[r] = 0.0f;
        const float4* wrow = reinterpret_cast<const float4*>(&Wih[(size_t)h * INPUT]);
        #pragma unroll
        for (int k4 = 0; k4 < INPUT / 4; k4++) {
            float4 w = wrow[k4];
            #pragma unroll
            for (int r = 0; r < 16; r++) {
                float4 xv = *reinterpret_cast<const float4*>(&xs[r][k4 * 4]);
                acc[r] = fmaf(w.x, xv.x, acc[r]); acc[r] = fmaf(w.y, xv.y, acc[r]);
                acc[r] = fmaf(w.z, xv.z, acc[r]); acc[r] = fmaf(w.w, xv.w, acc[r]);
            }
        }
        #pragma unroll
        for (int r = 0; r < 16; r++)
            out[(size_t)(bt0 + r) * HID + h] = acc[r] + bias;
    }
}

// W fp32 -> fp16 hi + fp16 lo*2^11 (lo scaled to stay in fp16 normal range)
__global__ __launch_bounds__(256) void wconv_kernel(
    const float* __restrict__ W, __half* __restrict__ hi, __half* __restrict__ lo)
{
    int i = blockIdx.x * 256 + threadIdx.x;
    float w = W[i];
    __half h = __float2half_rn(w);
    hi[i] = h;
    lo[i] = __float2half_rn((w - __half2float(h)) * 2048.0f);
}

// ---------------------------------------------------------------------------
// smem layout (bytes). A/W chunks are [32 rows][128B], granule swizzle g^(r&7).
// W: 6 arrays (hi/lo x 3 mats) x 8 chunks x 4KB = 192KB, block idx = mh*8+c.
// A: 2 sets x 4 chunks x 4KB = 32KB. Reduction (4KB) ALIASES tail of set 1.
#define SM_BIAS  0                             // 128 B
#define SM_W     128
#define W_BLOCK  4096
#define SM_A     (SM_W + 48 * W_BLOCK)         // 196736
#define SM_RED   (SM_A + 32768 - 4096)         // aliases set1 chunk3
#define SM_TOTAL (SM_A + 32768)                // 229504 <= 232448

// A-chunk staging (256 threads): one uint4 per thread per 4KB chunk
__device__ __forceinline__ uint4 sr_load(const __half* __restrict__ src, int b0, int kc) {
    const int r = threadIdx.x >> 3, g = threadIdx.x & 7;
    return __ldcg(reinterpret_cast<const uint4*>(src + (size_t)(b0 + r) * HID + kc) + g);
}
__device__ __forceinline__ void sr_store(uint4 v, char* abuf) {
    const int r = threadIdx.x >> 3, g = threadIdx.x & 7;
    *reinterpret_cast<uint4*>(abuf + r * 128 + ((g ^ (r & 7)) * 16)) = v;
}

// per-lane fragment addressing
struct LaneAddr { int aOff, aXor, aKh, wOff, wXor, wKh, jbase; };

// One 64-k chunk, this warp's K-half: 3 ldmatrix.x4 + 4 HMMA into FOUR
// independent accumulator quads (hi/lo x 2 h-tiles).
__device__ __forceinline__ void compute_chunk(
    uint32_t aB, uint32_t wHiB, const LaneAddr& L, float* a0, float* a1)
{
    #pragma unroll
    for (int j = 0; j < 2; j++) {
        const int jj = L.jbase + j;
        uint32_t a[4], whi[4], wlo[4];
        const uint32_t ga = (uint32_t)(((2 * jj + L.aKh) ^ L.aXor) * 16);
        const uint32_t gw = (uint32_t)(((2 * jj + L.wKh) ^ L.wXor) * 16);
        ldm_x4(a, aB + L.aOff + ga);
        ldm_x4(whi, wHiB + L.wOff + gw);
        ldm_x4(wlo, wHiB + 8 * W_BLOCK + L.wOff + gw);   // lo block = hi + 8 blocks
        mma16816(a0 + 0, a, whi[0], whi[1]);   // A*Whi
        mma16816(a0 + 4, a, wlo[0], wlo[1]);   // A*Wlo (scaled 2^11)
        mma16816(a1 + 0, a, whi[2], whi[3]);
        mma16816(a1 + 4, a, wlo[2], wlo[3]);
    }
}

// ---------------------------------------------------------------------------
// Persistent HMMA wavefront kernel. grid (16, 8) = 128 CTAs x 256 threads.
// 8 warps: km = warp&1 (K half), wq = warp>>1 -> wm = wq&1 (b half),
// wn = wq>>1 (h half). Four 64-k chunks per sync (two 16KB buffer sets).
__global__ __launch_bounds__(256) void rnn_mma_persistent(
    const float* __restrict__ xp,
    const float* __restrict__ bih1, const float* __restrict__ bhh1)
{
    extern __shared__ char smem[];
    const uint32_t smem_base = smem_to_u32(smem);
    const int tid = threadIdx.x;
    const int h0  = blockIdx.x * 32;
    const int b0  = blockIdx.y * 32;
    const unsigned nblocks = gridDim.x * gridDim.y;

    if (tid < 32)
        *reinterpret_cast<float*>(smem + SM_BIAS + tid * 4) = bih1[h0 + tid] + bhh1[h0 + tid];

    // ---- build resident W tiles: block index = mh*8 + c, mh = matrix*2 + hilo
    {
        const int r = tid >> 3, g = tid & 7;
        const int gs = (g ^ (r & 7)) * 16;
        #pragma unroll 1
        for (int mh = 0; mh < 6; mh++) {
            const __half* src =
                (mh == 0) ? g_W0hi : (mh == 1) ? g_W0lo :
                (mh == 2) ? g_W1hi : (mh == 3) ? g_W1lo :
                (mh == 4) ? g_W2hi : g_W2lo;
            #pragma unroll 1
            for (int c = 0; c < 8; c++) {
                uint4 v = __ldg(reinterpret_cast<const uint4*>(
                    src + (size_t)(h0 + r) * HID + c * 64) + g);
                *reinterpret_cast<uint4*>(
                    smem + SM_W + (size_t)(mh * 8 + c) * W_BLOCK + r * 128 + gs) = v;
            }
        }
    }

    // ---- zero initial parity-1 states ----
    if (tid < 128) {
        const int r = tid >> 2, cb = (tid & 3) * 8;
        const size_t o = (size_t)HSZ + (size_t)(b0 + r) * HID + h0 + cb;
        const uint4 z = make_uint4(0, 0, 0, 0);
        __stcg(reinterpret_cast<uint4*>(g_hx + o), z);
        __stcg(reinterpret_cast<uint4*>(g_h1 + o), z);
    }
    __syncthreads();
    grid_barrier(nblocks);

    // lane/warp constants
    const int warp = tid >> 5, lane = tid & 31;
    const int km = warp & 1;          // K half
    const int wq = warp >> 1;         // output quadrant
    const int wm = wq & 1, wn = wq >> 1;
    LaneAddr L;
    {
        const int blk = lane >> 3, lr = lane & 7;
        const int aRow = wm * 16 + (blk & 1) * 8 + lr;
        const int wRow = wn * 16 + (blk >> 1) * 8 + lr;
        L.aOff = aRow * 128; L.aXor = aRow & 7; L.aKh = blk >> 1;
        L.wOff = wRow * 128; L.wXor = wRow & 7; L.wKh = blk & 1;
        L.jbase = km * 2;
    }
    const int erow = b0 + wm * 16 + (lane >> 2);
    const int ecol = h0 + wn * 16 + (lane & 3) * 2;
    float* red = reinterpret_cast<float*>(smem + SM_RED) + (wq * 32 + lane) * 8;

    for (int t = 0; t <= SEQ; t++) {
        const size_t l0in  = (size_t)((t + 1) & 1) * HSZ;
        const size_t l0out = (size_t)(t & 1) * HSZ;
        const int s = t - 1;
        const size_t xOff  = (size_t)(s & 1) * HSZ;
        const size_t l1in  = (size_t)((s + 1) & 1) * HSZ;
        const size_t l1out = (size_t)(s & 1) * HSZ;

        // prefetch: L0 group 0 (chunks 0-3), L1 group 0, xp epilogue values
        uint4 sa[4], sb[4];
        float2 xv[2][2];
        if (t < SEQ) {
            #pragma unroll
            for (int q = 0; q < 4; q++) sa[q] = sr_load(g_hx + l0in, b0, q * 64);
            if (km == 0) {
                #pragma unroll
                for (int tile = 0; tile < 2; tile++)
                    #pragma unroll
                    for (int half = 0; half < 2; half++)
                        xv[tile][half] = __ldg(reinterpret_cast<const float2*>(
                            &xp[((size_t)(erow + half * 8) * SEQ + t) * HID
                                + ecol + tile * 8]));
            }
        }
        if (t > 0) {
            #pragma unroll
            for (int q = 0; q < 4; q++) sb[q] = sr_load(g_hx + xOff, b0, q * 64);
        }

        // ================= layer 0, step t =================
        if (t < SEQ) {
            float acc0[8], acc1[8];
            #pragma unroll
            for (int i = 0; i < 8; i++) { acc0[i] = 0.f; acc1[i] = 0.f; }
            #pragma unroll 1
            for (int g = 0; g < 2; g++) {               // 4 chunks per group
                char* bset = smem + SM_A + (size_t)g * 16384;
                #pragma unroll
                for (int q = 0; q < 4; q++) sr_store(sa[q], bset + q * 4096);
                __syncthreads();
                if (g == 0) {
                    #pragma unroll
                    for (int q = 0; q < 4; q++)
                        sa[q] = sr_load(g_hx + l0in, b0, (4 + q) * 64);
                }
                #pragma unroll
                for (int q = 0; q < 4; q++)
                    compute_chunk(smem_base + SM_A + (uint32_t)g * 16384 + q * 4096,
                                  smem_base + SM_W + (uint32_t)(4 * g + q) * W_BLOCK,
                                  L, acc0, acc1);
            }
            __syncthreads();                             // set1 reads done (red alias)
            if (km == 1) {
                #pragma unroll
                for (int i = 0; i < 4; i++) {
                    red[i]     = acc0[i] + acc0[4 + i] * INV2048;
                    red[4 + i] = acc1[i] + acc1[4 + i] * INV2048;
                }
            }
            __syncthreads();
            if (km == 0) {
                #pragma unroll
                for (int tile = 0; tile < 2; tile++) {
                    const float* ac = tile ? acc1 : acc0;
                    const float* rd = red + tile * 4;
                    const int h = ecol + tile * 8;
                    #pragma unroll
                    for (int half = 0; half < 2; half++) {
                        const int b = erow + half * 8;
                        float c0 = ac[half * 2 + 0] + ac[4 + half * 2 + 0] * INV2048
                                 + rd[half * 2 + 0];
                        float c1 = ac[half * 2 + 1] + ac[4 + half * 2 + 1] * INV2048
                                 + rd[half * 2 + 1];
                        float v0 = tanhf(c0 + xv[tile][half].x);
                        float v1 = tanhf(c1 + xv[tile][half].y);
                        __half2 hh = __halves2half2(__float2half_rn(v0), __float2half_rn(v1));
                        __stcg(reinterpret_cast<uint32_t*>(g_hx + l0out + (size_t)b * HID + h),
                               *reinterpret_cast<uint32_t*>(&hh));
                    }
                }
            }
        }

        // ================= layer 1, step s = t-1 =================
        if (t > 0) {
            float acc0[8], acc1[8];
            #pragma unroll
            for (int i = 0; i < 8; i++) { acc0[i] = 0.f; acc1[i] = 0.f; }
            #pragma unroll 1
            for (int g = 0; g < 4; g++) {               // chunks 4g..4g+3
                char* bset = smem + SM_A + (size_t)(g & 1) * 16384;
                #pragma unroll
                for (int q = 0; q < 4; q++) sr_store(sb[q], bset + q * 4096);
                __syncthreads();
                if (g + 1 < 4) {
                    #pragma unroll
                    for (int q = 0; q < 4; q++) {
                        const int nc = 4 * (g + 1) + q;
                        sb[q] = (nc < 8) ? sr_load(g_hx + xOff, b0, nc * 64)
                                         : sr_load(g_h1 + l1in, b0, (nc & 7) * 64);
                    }
                }
                #pragma unroll
                for (int q = 0; q < 4; q++) {
                    const int c = 4 * g + q;
                    const int m = (c < 8) ? 1 : 2;       // W1 blocks 16-23, W2 32-39
                    compute_chunk(smem_base + SM_A + (uint32_t)(g & 1) * 16384 + q * 4096,
                                  smem_base + SM_W + (uint32_t)(m * 16 + (c & 7)) * W_BLOCK,
                                  L, acc0, acc1);
                }
            }
            __syncthreads();                             // set1 reads done (red alias)
            if (km == 1) {
                #pragma unroll
                for (int i = 0; i < 4; i++) {
                    red[i]     = acc0[i] + acc0[4 + i] * INV2048;
                    red[4 + i] = acc1[i] + acc1[4 + i] * INV2048;
                }
            }
            __syncthreads();
            if (km == 0) {
                #pragma unroll
                for (int tile = 0; tile < 2; tile++) {
                    const float* ac = tile ? acc1 : acc0;
                    const float* rd = red + tile * 4;
                    const int h = ecol + tile * 8;
                    const float2 ev = *reinterpret_cast<const float2*>(
                        smem + SM_BIAS + (h - h0) * 4);
                    #pragma unroll
                    for (int half = 0; half < 2; half++) {
                        const int b = erow + half * 8;
                        float c0 = ac[half * 2 + 0] + ac[4 + half * 2 + 0] * INV2048
                                 + rd[half * 2 + 0];
                        float c1 = ac[half * 2 + 1] + ac[4 + half * 2 + 1] * INV2048
                                 + rd[half * 2 + 1];
                        float v0 = tanhf(c0 + ev.x);
                        float v1 = tanhf(c1 + ev.y);
                        __half2 hh = __halves2half2(__float2half_rn(v0), __float2half_rn(v1));
                        const size_t o = l1out + (size_t)b * HID + h;
                        __stcg(reinterpret_cast<uint32_t*>(g_h1 + o),
                               *reinterpret_cast<uint32_t*>(&hh));
                        __stcg(reinterpret_cast<float2*>(g_h1f + o), make_float2(v0, v1));
                    }
                }
            }
        }

        grid_barrier(nblocks);
    }
}

// ---------------------------------------------------------------------------
__global__ __launch_bounds__(128) void fc_kernel(
    const float* __restrict__ h, const float* __restrict__ Wfc,
    const float* __restrict__ bfc, float* __restrict__ out)
{
    const int bq = blockIdx.x;
    const int tid = threadIdx.x;
    float s = 0.f;
    for (int k = tid; k < HID; k += 128)
        s = fmaf(h[(size_t)bq * HID + k], Wfc[k], s);
    #pragma unroll
    for (int o = 16; o > 0; o >>= 1) s += __shfl_xor_sync(0xffffffffu, s, o);
    __shared__ float red[4];
    if ((tid & 31) == 0) red[tid >> 5] = s;
    __syncthreads();
    if (tid == 0) out[bq] = red[0] + red[1] + red[2] + red[3] + bfc[0];
}

// ---------------------------------------------------------------------------
extern "C" void kernel_launch(void* const* d_in, const int* in_sizes, int n_in,
                              void* d_out, int out_size)
{
    const float* x    = (const float*)d_in[0];
    const float* Wih0 = (const float*)d_in[1];
    const float* Whh0 = (const float*)d_in[2];
    const float* bih0 = (const float*)d_in[3];
    const float* bhh0 = (const float*)d_in[4];
    const float* Wih1 = (const float*)d_in[5];
    const float* Whh1 = (const float*)d_in[6];
    const float* bih1 = (const float*)d_in[7];
    const float* bhh1 = (const float*)d_in[8];
    const float* Wfc  = (const float*)d_in[9];
    const float* bfc  = (const float*)d_in[10];
    float* out = (float*)d_out;

    float *seq0, *h1f;
    __half *w0h, *w0l, *w1h, *w1l, *w2h, *w2l;
    cudaGetSymbolAddress((void**)&seq0, g_seq0);
    cudaGetSymbolAddress((void**)&h1f,  g_h1f);
    cudaGetSymbolAddress((void**)&w0h, g_W0hi); cudaGetSymbolAddress((void**)&w0l, g_W0lo);
    cudaGetSymbolAddress((void**)&w1h, g_W1hi); cudaGetSymbolAddress((void**)&w1l, g_W1lo);
    cudaGetSymbolAddress((void**)&w2h, g_W2hi); cudaGetSymbolAddress((void**)&w2l, g_W2lo);

    cudaFuncSetAttribute(rnn_mma_persistent,
                         cudaFuncAttributeMaxDynamicSharedMemorySize, SM_TOTAL);

    xp0_kernel<<<(BATCH * SEQ) / 16, 256>>>(x, Wih0, bih0, bhh0, seq0);
    wconv_kernel<<<(HID * HID) / 256, 256>>>(Whh0, w0h, w0l);
    wconv_kernel<<<(HID * HID) / 256, 256>>>(Wih1, w1h, w1l);
    wconv_kernel<<<(HID * HID) / 256, 256>>>(Whh1, w2h, w2l);

    rnn_mma_persistent<<<dim3(16, 8), 256, SM_TOTAL>>>(seq0, bih1, bhh1);

    // L1 final step s = 511 (odd) -> fp32 state in parity-1 buffer
    fc_kernel<<<BATCH, 128>>>(h1f + HSZ, Wfc, bfc, out);

    (void)in_sizes; (void)n_in; (void)out_size;
}